// round 4
// baseline (speedup 1.0000x reference)
#include <cuda_runtime.h>
#include <cstdint>

#define N_NODES 2048
#define FDIM 256
#define HID 64
#define TEMPLATE 10

// -------- scratch (static device globals; no allocation) --------
__device__ float g_h3[FDIM];
// pa transposed AND duplicated: g_paTd[k][2*node] == g_paTd[k][2*node+1]
__device__ float g_paTd[HID * 2 * N_NODES];
// pb transposed: g_pbT[k][node]
__device__ float g_pbT[HID * N_NODES];

// =====================================================================
// packed f32x2 helpers (Blackwell FFMA2 path)
// =====================================================================
typedef unsigned long long u64;

__device__ __forceinline__ u64 pack2(float lo, float hi) {
    u64 r;
    asm("mov.b64 %0, {%1, %2};" : "=l"(r) : "f"(lo), "f"(hi));
    return r;
}
__device__ __forceinline__ u64 add2(u64 a, u64 b) {
    u64 r;
    asm("add.rn.f32x2 %0, %1, %2;" : "=l"(r) : "l"(a), "l"(b));
    return r;
}
__device__ __forceinline__ u64 fma2(u64 a, u64 b, u64 c) {
    u64 r;
    asm("fma.rn.f32x2 %0, %1, %2, %3;" : "=l"(r) : "l"(a), "l"(b), "l"(c));
    return r;
}
__device__ __forceinline__ u64 relu2(u64 x) {
    u64 r;
    asm("{\n\t"
        ".reg .f32 lo, hi;\n\t"
        "mov.b64 {lo, hi}, %1;\n\t"
        "max.f32 lo, lo, 0f00000000;\n\t"
        "max.f32 hi, hi, 0f00000000;\n\t"
        "mov.b64 %0, {lo, hi};\n\t"
        "}" : "=l"(r) : "l"(x));
    return r;
}
__device__ __forceinline__ void unpack2(u64 x, float& lo, float& hi) {
    asm("mov.b64 {%0, %1}, %2;" : "=f"(lo), "=f"(hi) : "l"(x));
}
__device__ __forceinline__ float sigmoid_fast(float x) {
    float t;
    asm("tanh.approx.f32 %0, %1;" : "=f"(t) : "f"(0.5f * x));
    return fmaf(0.5f, t, 0.5f);
}

// =====================================================================
// Kernel A: proto mean + collapsed GCN (A@X identity for identical rows).
// One block, 512 threads. ALL weights preloaded into registers up-front
// (independent of the data chain), so the only serial latency is
// sel -> cf -> proto. Layers are pure FMA on smem broadcasts.
// =====================================================================
__global__ __launch_bounds__(512) void gcn_kernel(
        const float* __restrict__ cf,  const int* __restrict__ sel,
        const float* __restrict__ w1, const float* __restrict__ b1,
        const float* __restrict__ w2, const float* __restrict__ b2,
        const float* __restrict__ w3, const float* __restrict__ b3) {
    __shared__ float proto[FDIM];
    __shared__ float red[8][HID];     // also reused flat (512) for layer3
    __shared__ float h1[HID];
    __shared__ float h2[HID];
    int t = threadIdx.x;  // 0..511

    // ---- start the critical data chain first ----
    int sidx[TEMPLATE];
    #pragma unroll
    for (int q = 0; q < TEMPLATE; q++) sidx[q] = sel[q];

    // ---- weight preloads (independent; overlap with chain) ----
    int o1 = t & 63, kq1 = t >> 6;          // layer1: 8 chunks x 32 k
    float wv1[32];
    #pragma unroll
    for (int kk = 0; kk < 32; kk++)
        wv1[kk] = w1[(size_t)(kq1 * 32 + kk) * HID + o1];

    float wv2[8];                            // layer2: 8 chunks x 8 k
    #pragma unroll
    for (int kk = 0; kk < 8; kk++)
        wv2[kk] = w2[(size_t)(kq1 * 8 + kk) * HID + o1];

    int o3 = t & 255, kh3 = t >> 8;          // layer3: 2 halves x 32 k
    float wv3[32];
    #pragma unroll
    for (int kk = 0; kk < 32; kk++)
        wv3[kk] = w3[(size_t)(kh3 * 32 + kk) * FDIM + o3];

    // ---- proto (t < 256): 10 independent row loads ----
    if (t < FDIM) {
        float s = 0.f;
        #pragma unroll
        for (int q = 0; q < TEMPLATE; q++)
            s += cf[(size_t)sidx[q] * FDIM + t];
        proto[t] = s * (1.0f / TEMPLATE);
    }
    __syncthreads();

    // layer1: 256 -> 64
    {
        const float* p = proto + kq1 * 32;
        float a0 = 0.f, a1 = 0.f, a2 = 0.f, a3 = 0.f;
        #pragma unroll
        for (int kk = 0; kk < 32; kk += 4) {
            a0 = fmaf(p[kk],     wv1[kk],     a0);
            a1 = fmaf(p[kk + 1], wv1[kk + 1], a1);
            a2 = fmaf(p[kk + 2], wv1[kk + 2], a2);
            a3 = fmaf(p[kk + 3], wv1[kk + 3], a3);
        }
        red[kq1][o1] = (a0 + a1) + (a2 + a3);
    }
    __syncthreads();
    if (t < HID) {
        float s = b1[t];
        #pragma unroll
        for (int c = 0; c < 8; c++) s += red[c][t];
        h1[t] = fmaxf(s, 0.f);
    }
    __syncthreads();

    // layer2: 64 -> 64
    {
        const float* p = h1 + kq1 * 8;
        float a0 = 0.f, a1 = 0.f;
        #pragma unroll
        for (int kk = 0; kk < 8; kk += 2) {
            a0 = fmaf(p[kk],     wv2[kk],     a0);
            a1 = fmaf(p[kk + 1], wv2[kk + 1], a1);
        }
        red[kq1][o1] = a0 + a1;
    }
    __syncthreads();
    if (t < HID) {
        float s = b2[t];
        #pragma unroll
        for (int c = 0; c < 8; c++) s += red[c][t];
        h2[t] = fmaxf(s, 0.f);
    }
    __syncthreads();

    // layer3: 64 -> 256 (reuse red as flat [512])
    {
        const float* p = h2 + kh3 * 32;
        float a0 = 0.f, a1 = 0.f, a2 = 0.f, a3 = 0.f;
        #pragma unroll
        for (int kk = 0; kk < 32; kk += 4) {
            a0 = fmaf(p[kk],     wv3[kk],     a0);
            a1 = fmaf(p[kk + 1], wv3[kk + 1], a1);
            a2 = fmaf(p[kk + 2], wv3[kk + 2], a2);
            a3 = fmaf(p[kk + 3], wv3[kk + 3], a3);
        }
        ((float*)red)[kh3 * 256 + o3] = (a0 + a1) + (a2 + a3);
    }
    __syncthreads();
    if (t < FDIM) {
        float a = ((float*)red)[t] + ((float*)red)[256 + t] + b3[t];
        g_h3[t] = 1.0f / (1.0f + __expf(-a));
    }
}

// =====================================================================
// Kernel B: build trig rows (to out) + pa/pb = trig @ ew1 halves.
// 8 rows per block (transposed smem tile tst[k][rr]), f32x2 accumulate.
// Writes pa transposed+duplicated, pb transposed. eb1 folded into pa.
// =====================================================================
#define RPB 8

__global__ __launch_bounds__(256) void trig_pab_kernel(
        const float* __restrict__ noise,
        const float* __restrict__ ew1,
        const float* __restrict__ eb1,
        float* __restrict__ trig_out) {
    __shared__ float tst[FDIM][RPB];      // transposed tile: [k][row] 8KB
    __shared__ float part[2][RPB][128];   // 8KB
    int b = blockIdx.x, t = threadIdx.x;
    int r0 = b * RPB;

    // fill tile: thread t owns feature k=t for all 8 rows
    {
        float h3v = g_h3[t];
        float v[RPB];
        #pragma unroll
        for (int rr = 0; rr < RPB; rr++) {
            int r = r0 + rr;
            float x = h3v;
            if (r >= TEMPLATE)
                x = fmaf(0.1f, noise[(size_t)(r - TEMPLATE) * FDIM + t], x);
            v[rr] = x;
            trig_out[(size_t)r * FDIM + t] = x;
        }
        *(float4*)&tst[t][0] = make_float4(v[0], v[1], v[2], v[3]);
        *(float4*)&tst[t][4] = make_float4(v[4], v[5], v[6], v[7]);
    }
    __syncthreads();

    // GEMM: o = t&127 (half 0 -> pa col, half 1 -> pb col), kh = t>>7
    int o = t & 127, kh = t >> 7;
    int half = o >> 6, oc = o & 63;
    const float* w = ew1 + ((size_t)half * FDIM + kh * 128) * HID + oc;

    u64 acc01 = 0, acc23 = 0, acc45 = 0, acc67 = 0;
    #pragma unroll 4
    for (int k2 = 0; k2 < 128; k2++) {
        int kk = kh * 128 + k2;
        float wv = w[(size_t)k2 * HID];
        u64 ww = pack2(wv, wv);
        ulonglong2 rA = *(const ulonglong2*)&tst[kk][0];  // rows 0..3
        ulonglong2 rB = *(const ulonglong2*)&tst[kk][4];  // rows 4..7
        acc01 = fma2(rA.x, ww, acc01);
        acc23 = fma2(rA.y, ww, acc23);
        acc45 = fma2(rB.x, ww, acc45);
        acc67 = fma2(rB.y, ww, acc67);
    }
    {
        float a0, a1; unpack2(acc01, a0, a1);
        float a2, a3; unpack2(acc23, a2, a3);
        float a4, a5; unpack2(acc45, a4, a5);
        float a6, a7; unpack2(acc67, a6, a7);
        part[kh][0][o] = a0; part[kh][1][o] = a1;
        part[kh][2][o] = a2; part[kh][3][o] = a3;
        part[kh][4][o] = a4; part[kh][5][o] = a5;
        part[kh][6][o] = a6; part[kh][7][o] = a7;
    }
    __syncthreads();

    // finalize + transpose-store
    #pragma unroll
    for (int i = t; i < RPB * 128; i += 256) {
        int rr = i >> 7, oo = i & 127;
        float v = part[0][rr][oo] + part[1][rr][oo];
        int hh = oo >> 6, c = oo & 63;
        int node = r0 + rr;
        if (hh == 0) {
            v += eb1[c];
            g_paTd[(size_t)c * (2 * N_NODES) + 2 * node]     = v;
            g_paTd[(size_t)c * (2 * N_NODES) + 2 * node + 1] = v;
        } else {
            g_pbT[(size_t)c * N_NODES + node] = v;
        }
    }
}

// =====================================================================
// Kernel C: pairwise edge MLP over the upper triangle, f32x2.
// 64x64 tile per block, 256 threads, per-thread 4 i x 4 j (2 packed-j).
// a comes pre-duplicated from smem (no pack MOVs); smem exactly 48KB.
// =====================================================================
#define TILE 64

__global__ __launch_bounds__(256) void edge_kernel(
        const float* __restrict__ ew2,
        const float* __restrict__ eb2,
        float* __restrict__ out) {
    int bi = blockIdx.y;
    int bj = blockIdx.x;
    if (bj < bi) return;    // need j > i

    __shared__ float paD_s[HID][2 * TILE];   // 32 KB, duplicated pairs
    __shared__ float pbT_s[HID][TILE];       // 16 KB

    int tid = threadIdx.x;

    // load tiles (coalesced rows)
    {
        const float* paG = g_paTd + (size_t)bi * (2 * TILE);
        #pragma unroll
        for (int it = 0; it < 8; it++) {
            int idx = tid + it * 256;        // 2048 float4 slots
            int k = idx >> 5, c4 = (idx & 31) << 2;
            *(float4*)&paD_s[k][c4] =
                *(const float4*)(paG + (size_t)k * (2 * N_NODES) + c4);
        }
        const float* pbG = g_pbT + (size_t)bj * TILE;
        #pragma unroll
        for (int it = 0; it < 4; it++) {
            int idx = tid + it * 256;        // 1024 float4 slots
            int k = idx >> 4, c4 = (idx & 15) << 2;
            *(float4*)&pbT_s[k][c4] =
                *(const float4*)(pbG + (size_t)k * N_NODES + c4);
        }
    }
    float c0 = eb2[0];
    __syncthreads();

    int ti = tid & 15;    // i-group: i = 4*ti + r
    int tj = tid >> 4;    // j-group: j = 4*tj + 2*p (+0/1)

    u64 acc[4][2];
    #pragma unroll
    for (int r = 0; r < 4; r++) { acc[r][0] = 0ull; acc[r][1] = 0ull; }

    #pragma unroll
    for (int k4 = 0; k4 < HID; k4 += 4) {
        float4 w4 = __ldg((const float4*)&ew2[k4]);
        #pragma unroll
        for (int kk = 0; kk < 4; kk++) {
            int k = k4 + kk;
            float wk = (kk == 0) ? w4.x : (kk == 1) ? w4.y : (kk == 2) ? w4.z : w4.w;
            u64 ww = pack2(wk, wk);
            ulonglong2 a01 = *(const ulonglong2*)&paD_s[k][8 * ti];      // (a0,a0),(a1,a1)
            ulonglong2 a23 = *(const ulonglong2*)&paD_s[k][8 * ti + 4];  // (a2,a2),(a3,a3)
            ulonglong2 bb  = *(const ulonglong2*)&pbT_s[k][4 * tj];      // (b0,b1),(b2,b3)
            u64 ad[4] = { a01.x, a01.y, a23.x, a23.y };
            #pragma unroll
            for (int r = 0; r < 4; r++) {
                acc[r][0] = fma2(relu2(add2(ad[r], bb.x)), ww, acc[r][0]);
                acc[r][1] = fma2(relu2(add2(ad[r], bb.y)), ww, acc[r][1]);
            }
        }
    }

    int ibase = bi * TILE;
    int jbase = bj * TILE;
    #pragma unroll
    for (int r = 0; r < 4; r++) {
        int i = ibase + 4 * ti + r;
        // linear index of (i,j) in row-major upper triangle (k=1):
        //   m = i*(N-1) - i*(i-1)/2 + (j - i - 1)
        int off = i * (N_NODES - 1) - ((i * (i - 1)) >> 1) - i - 1;
        #pragma unroll
        for (int p = 0; p < 2; p++) {
            int j0 = jbase + 4 * tj + 2 * p;
            float lo, hi;
            unpack2(acc[r][p], lo, hi);
            if (j0     > i) out[off + j0]     = sigmoid_fast(lo + c0);
            if (j0 + 1 > i) out[off + j0 + 1] = sigmoid_fast(hi + c0);
        }
    }
}

// =====================================================================
// Launch
// =====================================================================
extern "C" void kernel_launch(void* const* d_in, const int* in_sizes, int n_in,
                              void* d_out, int out_size) {
    const float* clean_features = (const float*)d_in[0];
    const int*   selected_nodes = (const int*)  d_in[1];
    const float* noise          = (const float*)d_in[2];
    const float* gcn1_w         = (const float*)d_in[3];
    const float* gcn1_b         = (const float*)d_in[4];
    const float* gcn2_w         = (const float*)d_in[5];
    const float* gcn2_b         = (const float*)d_in[6];
    const float* gcn3_w         = (const float*)d_in[7];
    const float* gcn3_b         = (const float*)d_in[8];
    const float* ew1            = (const float*)d_in[9];
    const float* eb1            = (const float*)d_in[10];
    const float* ew2            = (const float*)d_in[11];
    const float* eb2            = (const float*)d_in[12];

    float* out = (float*)d_out;
    float* trig_out = out;                    // [2048, 256]
    float* edge_out = out + N_NODES * FDIM;   // [2096128]

    gcn_kernel<<<1, 512>>>(clean_features, selected_nodes,
                           gcn1_w, gcn1_b, gcn2_w, gcn2_b, gcn3_w, gcn3_b);

    trig_pab_kernel<<<N_NODES / RPB, 256>>>(noise, ew1, eb1, trig_out);

    dim3 grid(N_NODES / TILE, N_NODES / TILE);   // 32 x 32, lower half exits
    edge_kernel<<<grid, 256>>>(ew2, eb2, edge_out);
}

// round 6
// speedup vs baseline: 1.1445x; 1.1445x over previous
#include <cuda_runtime.h>
#include <cstdint>

#define N_NODES 2048
#define FDIM 256
#define HID 64
#define TEMPLATE 10

// -------- scratch (static device globals; no allocation) --------
__device__ float g_h3[FDIM];
__device__ float g_pa[N_NODES * HID];   // trig @ ew1[:256], eb1 folded in
__device__ float g_pb[N_NODES * HID];   // trig @ ew1[256:]

__device__ __forceinline__ float sigmoid_fast(float x) {
    float t;
    asm("tanh.approx.f32 %0, %1;" : "=f"(t) : "f"(0.5f * x));
    return fmaf(0.5f, t, 0.5f);
}

// =====================================================================
// Kernel A: proto mean + collapsed GCN (A@X identity for identical rows).
// One block, 1024 threads. Weights preloaded into registers (36/thread,
// no spill under the 64-reg cap). Only serial latency: sel -> cf -> proto.
// =====================================================================
__global__ __launch_bounds__(1024) void gcn_kernel(
        const float* __restrict__ cf,  const int* __restrict__ sel,
        const float* __restrict__ w1, const float* __restrict__ b1,
        const float* __restrict__ w2, const float* __restrict__ b2,
        const float* __restrict__ w3, const float* __restrict__ b3) {
    __shared__ float proto[FDIM];
    __shared__ float red[16][HID];    // 4KB; reused flat [1024] for layer3
    __shared__ float h1[HID];
    __shared__ float h2[HID];
    int t = threadIdx.x;  // 0..1023

    // ---- start the critical data chain first ----
    int sidx[TEMPLATE];
    #pragma unroll
    for (int q = 0; q < TEMPLATE; q++) sidx[q] = sel[q];

    // ---- weight preloads (independent of data chain; fully overlapped) ----
    int o1 = t & 63, kq1 = t >> 6;       // layer1/2: 16 chunks
    float wv1[16];                       // layer1: 16 k's per thread
    #pragma unroll
    for (int kk = 0; kk < 16; kk++)
        wv1[kk] = w1[(size_t)(kq1 * 16 + kk) * HID + o1];

    float wv2[4];                        // layer2: 4 k's per thread
    #pragma unroll
    for (int kk = 0; kk < 4; kk++)
        wv2[kk] = w2[(size_t)(kq1 * 4 + kk) * HID + o1];

    int o3 = t & 255, kh3 = t >> 8;      // layer3: 4 chunks x 16 k
    float wv3[16];
    #pragma unroll
    for (int kk = 0; kk < 16; kk++)
        wv3[kk] = w3[(size_t)(kh3 * 16 + kk) * FDIM + o3];

    // ---- proto (t < 256): 10 independent row loads ----
    if (t < FDIM) {
        float s = 0.f;
        #pragma unroll
        for (int q = 0; q < TEMPLATE; q++)
            s += cf[(size_t)sidx[q] * FDIM + t];
        proto[t] = s * (1.0f / TEMPLATE);
    }
    __syncthreads();

    // layer1: 256 -> 64  (split-K over 16 chunks of 16)
    {
        const float* p = proto + kq1 * 16;
        float a0 = 0.f, a1 = 0.f, a2 = 0.f, a3 = 0.f;
        #pragma unroll
        for (int kk = 0; kk < 16; kk += 4) {
            a0 = fmaf(p[kk],     wv1[kk],     a0);
            a1 = fmaf(p[kk + 1], wv1[kk + 1], a1);
            a2 = fmaf(p[kk + 2], wv1[kk + 2], a2);
            a3 = fmaf(p[kk + 3], wv1[kk + 3], a3);
        }
        red[kq1][o1] = (a0 + a1) + (a2 + a3);
    }
    __syncthreads();
    if (t < HID) {
        float s = b1[t];
        #pragma unroll
        for (int c = 0; c < 16; c++) s += red[c][t];
        h1[t] = fmaxf(s, 0.f);
    }
    __syncthreads();

    // layer2: 64 -> 64  (split-K over 16 chunks of 4)
    {
        const float* p = h1 + kq1 * 4;
        float a0 = fmaf(p[0], wv2[0], 0.f);
        float a1 = fmaf(p[1], wv2[1], 0.f);
        a0 = fmaf(p[2], wv2[2], a0);
        a1 = fmaf(p[3], wv2[3], a1);
        red[kq1][o1] = a0 + a1;
    }
    __syncthreads();
    if (t < HID) {
        float s = b2[t];
        #pragma unroll
        for (int c = 0; c < 16; c++) s += red[c][t];
        h2[t] = fmaxf(s, 0.f);
    }
    __syncthreads();

    // layer3: 64 -> 256  (split-K over 4 chunks of 16; red reused flat)
    {
        const float* p = h2 + kh3 * 16;
        float a0 = 0.f, a1 = 0.f, a2 = 0.f, a3 = 0.f;
        #pragma unroll
        for (int kk = 0; kk < 16; kk += 4) {
            a0 = fmaf(p[kk],     wv3[kk],     a0);
            a1 = fmaf(p[kk + 1], wv3[kk + 1], a1);
            a2 = fmaf(p[kk + 2], wv3[kk + 2], a2);
            a3 = fmaf(p[kk + 3], wv3[kk + 3], a3);
        }
        ((float*)red)[kh3 * 256 + o3] = (a0 + a1) + (a2 + a3);
    }
    __syncthreads();
    if (t < FDIM) {
        float a = ((float*)red)[t] + ((float*)red)[256 + t] +
                  ((float*)red)[512 + t] + ((float*)red)[768 + t] + b3[t];
        g_h3[t] = 1.0f / (1.0f + __expf(-a));
    }
}

// =====================================================================
// Kernel B: build trig rows (to out) + pa/pb = trig @ ew1 halves.
// 8 rows per block, 256 blocks, 256 threads. Scalar FFMA, broadcast LDS.
// eb1 folded into pa. Outputs in [node][k] layout for the edge kernel.
// =====================================================================
#define RPB 8

__global__ __launch_bounds__(256) void trig_pab_kernel(
        const float* __restrict__ noise,
        const float* __restrict__ ew1,
        const float* __restrict__ eb1,
        float* __restrict__ trig_out) {
    __shared__ float ts[RPB][FDIM];          // 8 KB
    __shared__ float part[2][RPB][128];      // 8 KB
    int b = blockIdx.x, t = threadIdx.x;
    int r0 = b * RPB;

    float h3v = g_h3[t];
    #pragma unroll
    for (int rr = 0; rr < RPB; rr++) {
        int r = r0 + rr;
        float v = h3v;
        if (r >= TEMPLATE) v = fmaf(0.1f, noise[(size_t)(r - TEMPLATE) * FDIM + t], v);
        ts[rr][t] = v;
        trig_out[(size_t)r * FDIM + t] = v;
    }
    __syncthreads();

    // o = t & 127 (0..63 -> pa col, 64..127 -> pb col), kh = t >> 7
    int o = t & 127, kh = t >> 7;
    int half = o >> 6, oc = o & 63;
    const float* w = ew1 + ((size_t)half * FDIM + kh * 128) * HID + oc;
    const float* p = &ts[0][kh * 128];

    float acc[RPB];
    #pragma unroll
    for (int rr = 0; rr < RPB; rr++) acc[rr] = 0.f;

    #pragma unroll 4
    for (int k = 0; k < 128; k++) {
        float wv = w[(size_t)k * HID];
        #pragma unroll
        for (int rr = 0; rr < RPB; rr++)
            acc[rr] = fmaf(p[rr * FDIM + k], wv, acc[rr]);
    }
    #pragma unroll
    for (int rr = 0; rr < RPB; rr++) part[kh][rr][o] = acc[rr];
    __syncthreads();

    // finalize: coalesced [node][k] stores
    #pragma unroll
    for (int i = t; i < RPB * 128; i += 256) {
        int rr = i >> 7, oo = i & 127;
        float v = part[0][rr][oo] + part[1][rr][oo];
        int hh = oo >> 6, c = oo & 63;
        int node = r0 + rr;
        if (hh == 0) g_pa[(size_t)node * HID + c] = v + eb1[c];
        else         g_pb[(size_t)node * HID + c] = v;
    }
}

// =====================================================================
// Kernel C: pairwise edge MLP over the upper triangle (proven scalar).
// 64x64 tile per block, 256 threads, 4x4 micro-tile per thread.
// =====================================================================
#define TILE 64
#define PADK 68   // padded k-stride: conflict-free float4 LDS

__global__ __launch_bounds__(256) void edge_kernel(const float* __restrict__ ew2,
                                                   const float* __restrict__ eb2,
                                                   float* __restrict__ out) {
    int bi = blockIdx.y;
    int bj = blockIdx.x;
    if (bi > bj) return;   // only upper-triangular tiles

    __shared__ float pa_s[TILE][PADK];
    __shared__ float pb_s[TILE][PADK];
    __shared__ float w2_s[HID];

    int tid = threadIdx.x;

    const float* paG = g_pa + bi * TILE * HID;
    const float* pbG = g_pb + bj * TILE * HID;
    #pragma unroll
    for (int it = 0; it < 4; it++) {
        int idx = tid + it * 256;          // 0..1023 float4s
        int row = idx >> 4;                // 16 float4 per row
        int kq  = (idx & 15) << 2;
        float4 va = *(const float4*)(paG + row * HID + kq);
        pa_s[row][kq] = va.x; pa_s[row][kq+1] = va.y; pa_s[row][kq+2] = va.z; pa_s[row][kq+3] = va.w;
        float4 vb = *(const float4*)(pbG + row * HID + kq);
        pb_s[row][kq] = vb.x; pb_s[row][kq+1] = vb.y; pb_s[row][kq+2] = vb.z; pb_s[row][kq+3] = vb.w;
    }
    if (tid < HID) w2_s[tid] = ew2[tid];
    float c0 = eb2[0];
    __syncthreads();

    int tx = tid & 15;   // j-direction
    int ty = tid >> 4;   // i-direction

    float acc[4][4];
    #pragma unroll
    for (int r = 0; r < 4; r++)
        #pragma unroll
        for (int c = 0; c < 4; c++) acc[r][c] = 0.f;

    #pragma unroll 4
    for (int kq = 0; kq < HID; kq += 4) {
        float4 w4 = *(const float4*)&w2_s[kq];
        float4 A0 = *(const float4*)&pa_s[ty     ][kq];
        float4 A1 = *(const float4*)&pa_s[ty + 16][kq];
        float4 A2 = *(const float4*)&pa_s[ty + 32][kq];
        float4 A3 = *(const float4*)&pa_s[ty + 48][kq];
        float4 B0 = *(const float4*)&pb_s[tx     ][kq];
        float4 B1 = *(const float4*)&pb_s[tx + 16][kq];
        float4 B2 = *(const float4*)&pb_s[tx + 32][kq];
        float4 B3 = *(const float4*)&pb_s[tx + 48][kq];

#define EDGE_STEP(COMP)                                                          \
        {                                                                        \
            float a0 = A0.COMP, a1 = A1.COMP, a2 = A2.COMP, a3 = A3.COMP;        \
            float b0 = B0.COMP, b1 = B1.COMP, b2 = B2.COMP, b3 = B3.COMP;        \
            float w  = w4.COMP;                                                  \
            acc[0][0] = fmaf(fmaxf(a0 + b0, 0.f), w, acc[0][0]);                 \
            acc[0][1] = fmaf(fmaxf(a0 + b1, 0.f), w, acc[0][1]);                 \
            acc[0][2] = fmaf(fmaxf(a0 + b2, 0.f), w, acc[0][2]);                 \
            acc[0][3] = fmaf(fmaxf(a0 + b3, 0.f), w, acc[0][3]);                 \
            acc[1][0] = fmaf(fmaxf(a1 + b0, 0.f), w, acc[1][0]);                 \
            acc[1][1] = fmaf(fmaxf(a1 + b1, 0.f), w, acc[1][1]);                 \
            acc[1][2] = fmaf(fmaxf(a1 + b2, 0.f), w, acc[1][2]);                 \
            acc[1][3] = fmaf(fmaxf(a1 + b3, 0.f), w, acc[1][3]);                 \
            acc[2][0] = fmaf(fmaxf(a2 + b0, 0.f), w, acc[2][0]);                 \
            acc[2][1] = fmaf(fmaxf(a2 + b1, 0.f), w, acc[2][1]);                 \
            acc[2][2] = fmaf(fmaxf(a2 + b2, 0.f), w, acc[2][2]);                 \
            acc[2][3] = fmaf(fmaxf(a2 + b3, 0.f), w, acc[2][3]);                 \
            acc[3][0] = fmaf(fmaxf(a3 + b0, 0.f), w, acc[3][0]);                 \
            acc[3][1] = fmaf(fmaxf(a3 + b1, 0.f), w, acc[3][1]);                 \
            acc[3][2] = fmaf(fmaxf(a3 + b2, 0.f), w, acc[3][2]);                 \
            acc[3][3] = fmaf(fmaxf(a3 + b3, 0.f), w, acc[3][3]);                 \
        }
        EDGE_STEP(x)
        EDGE_STEP(y)
        EDGE_STEP(z)
        EDGE_STEP(w)
#undef EDGE_STEP
    }

    int ibase = bi * TILE;
    int jbase = bj * TILE;
    #pragma unroll
    for (int r = 0; r < 4; r++) {
        int i = ibase + ty + r * 16;
        // linear index of (i,j) in row-major upper triangle (k=1):
        //   m = i*(N-1) - i*(i-1)/2 + (j - i - 1)
        int off = i * (N_NODES - 1) - ((i * (i - 1)) >> 1) - i - 1;
        #pragma unroll
        for (int c = 0; c < 4; c++) {
            int j = jbase + tx + c * 16;
            if (j > i) {
                out[off + j] = sigmoid_fast(acc[r][c] + c0);
            }
        }
    }
}

// =====================================================================
// Launch
// =====================================================================
extern "C" void kernel_launch(void* const* d_in, const int* in_sizes, int n_in,
                              void* d_out, int out_size) {
    const float* clean_features = (const float*)d_in[0];
    const int*   selected_nodes = (const int*)  d_in[1];
    const float* noise          = (const float*)d_in[2];
    const float* gcn1_w         = (const float*)d_in[3];
    const float* gcn1_b         = (const float*)d_in[4];
    const float* gcn2_w         = (const float*)d_in[5];
    const float* gcn2_b         = (const float*)d_in[6];
    const float* gcn3_w         = (const float*)d_in[7];
    const float* gcn3_b         = (const float*)d_in[8];
    const float* ew1            = (const float*)d_in[9];
    const float* eb1            = (const float*)d_in[10];
    const float* ew2            = (const float*)d_in[11];
    const float* eb2            = (const float*)d_in[12];

    float* out = (float*)d_out;
    float* trig_out = out;                    // [2048, 256]
    float* edge_out = out + N_NODES * FDIM;   // [2096128]

    gcn_kernel<<<1, 1024>>>(clean_features, selected_nodes,
                            gcn1_w, gcn1_b, gcn2_w, gcn2_b, gcn3_w, gcn3_b);

    trig_pab_kernel<<<N_NODES / RPB, 256>>>(noise, ew1, eb1, trig_out);

    dim3 grid(N_NODES / TILE, N_NODES / TILE);   // 32 x 32, lower half exits
    edge_kernel<<<grid, 256>>>(ew2, eb2, edge_out);
}

// round 7
// speedup vs baseline: 1.1681x; 1.0206x over previous
#include <cuda_runtime.h>
#include <cstdint>

#define N_NODES 2048
#define FDIM 256
#define HID 64
#define TEMPLATE 10

// -------- scratch (static device globals; no allocation) --------
__device__ float g_h3[FDIM];
__device__ float g_ha[HID];             // h3 @ ew1[:256] + eb1
__device__ float g_hb[HID];             // h3 @ ew1[256:]
__device__ float g_pa[N_NODES * HID];   // 0.1*noise @ ew1[:256]  (rows 0-9 zero)
__device__ float g_pb[N_NODES * HID];   // 0.1*noise @ ew1[256:]  (rows 0-9 zero)

__device__ __forceinline__ float sigmoid_fast(float x) {
    float t;
    asm("tanh.approx.f32 %0, %1;" : "=f"(t) : "f"(0.5f * x));
    return fmaf(0.5f, t, 0.5f);
}

// =====================================================================
// Kernel 1 (merged): block 0 = GCN (latency-bound, hidden behind the
// rest); blocks 1..255 = noise GEMM (0.1*noise @ ew1) + trig noise rows.
// 1024 threads per block.
// =====================================================================
#define RPB 8   // noise rows per block

__global__ __launch_bounds__(1024) void merged_kernel(
        const float* __restrict__ cf,  const int* __restrict__ sel,
        const float* __restrict__ w1, const float* __restrict__ b1,
        const float* __restrict__ w2, const float* __restrict__ b2,
        const float* __restrict__ w3, const float* __restrict__ b3,
        const float* __restrict__ noise,
        const float* __restrict__ ew1,
        const float* __restrict__ eb1,
        float* __restrict__ trig_out) {
    // noise-path smem
    __shared__ float tst[FDIM][9];          // transposed 0.1*noise tile (pad 9)
    __shared__ float part[8][RPB][128];     // GEMM partials [chunk][row][col]
    // gcn-path smem
    __shared__ float proto[FDIM];
    __shared__ float red[16][HID];          // reused flat [1024]
    __shared__ float h1s[HID];
    __shared__ float h2s[HID];
    __shared__ float h3s[FDIM];

    int t = threadIdx.x;  // 0..1023
    int b = blockIdx.x;

    if (b == 0) {
        // ================= GCN block =================
        int sidx[TEMPLATE];
        #pragma unroll
        for (int q = 0; q < TEMPLATE; q++) sidx[q] = sel[q];

        // weight preloads (independent of the data chain)
        int o1 = t & 63, kq1 = t >> 6;       // 16 chunks
        float wv1[16];
        #pragma unroll
        for (int kk = 0; kk < 16; kk++)
            wv1[kk] = w1[(size_t)(kq1 * 16 + kk) * HID + o1];
        float wv2[4];
        #pragma unroll
        for (int kk = 0; kk < 4; kk++)
            wv2[kk] = w2[(size_t)(kq1 * 4 + kk) * HID + o1];
        int o3 = t & 255, kh3 = t >> 8;      // 4 chunks x 16 k
        float wv3[16];
        #pragma unroll
        for (int kk = 0; kk < 16; kk++)
            wv3[kk] = w3[(size_t)(kh3 * 16 + kk) * FDIM + o3];

        if (t < FDIM) {
            float s = 0.f;
            #pragma unroll
            for (int q = 0; q < TEMPLATE; q++)
                s += cf[(size_t)sidx[q] * FDIM + t];
            proto[t] = s * (1.0f / TEMPLATE);
        }
        __syncthreads();

        // layer1: 256 -> 64
        {
            const float* p = proto + kq1 * 16;
            float a0 = 0.f, a1 = 0.f, a2 = 0.f, a3 = 0.f;
            #pragma unroll
            for (int kk = 0; kk < 16; kk += 4) {
                a0 = fmaf(p[kk],     wv1[kk],     a0);
                a1 = fmaf(p[kk + 1], wv1[kk + 1], a1);
                a2 = fmaf(p[kk + 2], wv1[kk + 2], a2);
                a3 = fmaf(p[kk + 3], wv1[kk + 3], a3);
            }
            red[kq1][o1] = (a0 + a1) + (a2 + a3);
        }
        __syncthreads();
        if (t < HID) {
            float s = b1[t];
            #pragma unroll
            for (int c = 0; c < 16; c++) s += red[c][t];
            h1s[t] = fmaxf(s, 0.f);
        }
        __syncthreads();

        // layer2: 64 -> 64
        {
            const float* p = h1s + kq1 * 4;
            float a0 = fmaf(p[0], wv2[0], 0.f);
            float a1 = fmaf(p[1], wv2[1], 0.f);
            a0 = fmaf(p[2], wv2[2], a0);
            a1 = fmaf(p[3], wv2[3], a1);
            red[kq1][o1] = a0 + a1;
        }
        __syncthreads();
        if (t < HID) {
            float s = b2[t];
            #pragma unroll
            for (int c = 0; c < 16; c++) s += red[c][t];
            h2s[t] = fmaxf(s, 0.f);
        }
        __syncthreads();

        // layer3: 64 -> 256
        {
            const float* p = h2s + kh3 * 16;
            float a0 = 0.f, a1 = 0.f, a2 = 0.f, a3 = 0.f;
            #pragma unroll
            for (int kk = 0; kk < 16; kk += 4) {
                a0 = fmaf(p[kk],     wv3[kk],     a0);
                a1 = fmaf(p[kk + 1], wv3[kk + 1], a1);
                a2 = fmaf(p[kk + 2], wv3[kk + 2], a2);
                a3 = fmaf(p[kk + 3], wv3[kk + 3], a3);
            }
            ((float*)red)[kh3 * 256 + o3] = (a0 + a1) + (a2 + a3);
        }
        __syncthreads();
        if (t < FDIM) {
            float a = ((float*)red)[t] + ((float*)red)[256 + t] +
                      ((float*)red)[512 + t] + ((float*)red)[768 + t] + b3[t];
            float v = 1.0f / (1.0f + __expf(-a));
            h3s[t] = v;
            g_h3[t] = v;
        }
        __syncthreads();

        // ha = h3 @ ew1[:256] + eb1 ; hb = h3 @ ew1[256:]
        {
            int o2 = t & 127, c2 = t >> 7;          // 8 chunks x 32 k
            int half = o2 >> 6, oc = o2 & 63;
            const float* w = ew1 + ((size_t)half * FDIM + c2 * 32) * HID + oc;
            const float* p = h3s + c2 * 32;
            float a0 = 0.f, a1 = 0.f;
            #pragma unroll
            for (int kk = 0; kk < 32; kk += 2) {
                a0 = fmaf(p[kk],     w[(size_t)(kk)     * HID], a0);
                a1 = fmaf(p[kk + 1], w[(size_t)(kk + 1) * HID], a1);
            }
            ((float*)red)[c2 * 128 + o2] = a0 + a1;
        }
        __syncthreads();
        if (t < 128) {
            int half = t >> 6, oc = t & 63;
            float s = 0.f;
            #pragma unroll
            for (int c = 0; c < 8; c++) s += ((float*)red)[c * 128 + t];
            if (half == 0) g_ha[oc] = s + eb1[oc];
            else           g_hb[oc] = s;
        }

        // trig rows 0..9 = h3 ; zero pa/pb rows 0..9
        if (t < FDIM) {
            float v = h3s[t];
            #pragma unroll
            for (int r = 0; r < TEMPLATE; r++)
                trig_out[(size_t)r * FDIM + t] = v;
        }
        if (t < TEMPLATE * HID) {
            g_pa[t] = 0.f;
            g_pb[t] = 0.f;
        }
        return;
    }

    // ================= noise GEMM blocks =================
    int r0 = TEMPLATE + (b - 1) * RPB;     // first node row of this block

    // load 0.1*noise tile (transposed), write trig rows (pre-h3)
    {
        int k = t & 255, g = t >> 8;       // g in 0..3, rows 2g, 2g+1
        #pragma unroll
        for (int rr2 = 0; rr2 < 2; rr2++) {
            int rr = 2 * g + rr2;
            int r = r0 + rr;
            if (r < N_NODES) {
                float v = 0.1f * noise[(size_t)(r - TEMPLATE) * FDIM + k];
                tst[k][rr] = v;
                trig_out[(size_t)r * FDIM + k] = v;
            } else {
                tst[k][rr] = 0.f;
            }
        }
    }
    __syncthreads();

    // GEMM: o = t&127 (half 0 -> pa, half 1 -> pb), c = t>>7 (8 chunks x 32 k)
    {
        int o = t & 127, c = t >> 7;
        int half = o >> 6, oc = o & 63;
        const float* w = ew1 + ((size_t)half * FDIM + c * 32) * HID + oc;

        float acc[RPB];
        #pragma unroll
        for (int rr = 0; rr < RPB; rr++) acc[rr] = 0.f;

        #pragma unroll 4
        for (int kk = 0; kk < 32; kk++) {
            int k = c * 32 + kk;
            float wv = w[(size_t)kk * HID];
            #pragma unroll
            for (int rr = 0; rr < RPB; rr++)
                acc[rr] = fmaf(tst[k][rr], wv, acc[rr]);
        }
        #pragma unroll
        for (int rr = 0; rr < RPB; rr++) part[c][rr][o] = acc[rr];
    }
    __syncthreads();

    // reduce 8 chunks + coalesced store
    {
        int rr = t >> 7, oo = t & 127;     // 1024 threads = 8 rows x 128 cols
        int r = r0 + rr;
        if (r < N_NODES) {
            float s = 0.f;
            #pragma unroll
            for (int c = 0; c < 8; c++) s += part[c][rr][oo];
            int half = oo >> 6, oc = oo & 63;
            if (half == 0) g_pa[(size_t)r * HID + oc] = s;
            else           g_pb[(size_t)r * HID + oc] = s;
        }
    }
}

// =====================================================================
// Kernel 2: edge MLP on upper-tri tiles; lower-tri blocks do trig fixup
// (trig[10:] += h3). 64x64 tile, 256 threads, 4x4 micro-tile.
// Tile load folds +ha / +hb (so pa/pb globals hold only the noise part).
// =====================================================================
#define TILE 64
#define PADK 68

__global__ __launch_bounds__(256) void edge_kernel(const float* __restrict__ ew2,
                                                   const float* __restrict__ eb2,
                                                   float* __restrict__ trig_out,
                                                   float* __restrict__ out) {
    int bi = blockIdx.y;
    int bj = blockIdx.x;
    int tid = threadIdx.x;

    if (bi > bj) {
        // -------- trig fixup: trig[10:][:] += h3 --------
        int lid = ((bi * (bi - 1)) >> 1) + bj;                  // 0..495
        const int total = (N_NODES - TEMPLATE) * FDIM;          // 521728
        const int per = (total + 495) / 496;                    // 1052
        int start = lid * per;
        int end = start + per; if (end > total) end = total;
        for (int e = start + tid; e < end; e += 256) {
            int col = e & (FDIM - 1);
            int row = TEMPLATE + (e >> 8);
            trig_out[(size_t)row * FDIM + col] += __ldg(&g_h3[col]);
        }
        return;
    }

    __shared__ float pa_s[TILE][PADK];
    __shared__ float pb_s[TILE][PADK];
    __shared__ float w2_s[HID];

    const float* paG = g_pa + bi * TILE * HID;
    const float* pbG = g_pb + bj * TILE * HID;
    #pragma unroll
    for (int it = 0; it < 4; it++) {
        int idx = tid + it * 256;          // 0..1023 float4s
        int row = idx >> 4;                // 16 float4 per row
        int kq  = (idx & 15) << 2;
        float4 ha4 = __ldg((const float4*)&g_ha[kq]);
        float4 hb4 = __ldg((const float4*)&g_hb[kq]);
        float4 va = *(const float4*)(paG + row * HID + kq);
        pa_s[row][kq]   = va.x + ha4.x;
        pa_s[row][kq+1] = va.y + ha4.y;
        pa_s[row][kq+2] = va.z + ha4.z;
        pa_s[row][kq+3] = va.w + ha4.w;
        float4 vb = *(const float4*)(pbG + row * HID + kq);
        pb_s[row][kq]   = vb.x + hb4.x;
        pb_s[row][kq+1] = vb.y + hb4.y;
        pb_s[row][kq+2] = vb.z + hb4.z;
        pb_s[row][kq+3] = vb.w + hb4.w;
    }
    if (tid < HID) w2_s[tid] = ew2[tid];
    float c0 = eb2[0];
    __syncthreads();

    int tx = tid & 15;   // j-direction
    int ty = tid >> 4;   // i-direction

    float acc[4][4];
    #pragma unroll
    for (int r = 0; r < 4; r++)
        #pragma unroll
        for (int c = 0; c < 4; c++) acc[r][c] = 0.f;

    #pragma unroll 4
    for (int kq = 0; kq < HID; kq += 4) {
        float4 w4 = *(const float4*)&w2_s[kq];
        float4 A0 = *(const float4*)&pa_s[ty     ][kq];
        float4 A1 = *(const float4*)&pa_s[ty + 16][kq];
        float4 A2 = *(const float4*)&pa_s[ty + 32][kq];
        float4 A3 = *(const float4*)&pa_s[ty + 48][kq];
        float4 B0 = *(const float4*)&pb_s[tx     ][kq];
        float4 B1 = *(const float4*)&pb_s[tx + 16][kq];
        float4 B2 = *(const float4*)&pb_s[tx + 32][kq];
        float4 B3 = *(const float4*)&pb_s[tx + 48][kq];

#define EDGE_STEP(COMP)                                                          \
        {                                                                        \
            float a0 = A0.COMP, a1 = A1.COMP, a2 = A2.COMP, a3 = A3.COMP;        \
            float b0 = B0.COMP, b1 = B1.COMP, b2 = B2.COMP, b3 = B3.COMP;        \
            float w  = w4.COMP;                                                  \
            acc[0][0] = fmaf(fmaxf(a0 + b0, 0.f), w, acc[0][0]);                 \
            acc[0][1] = fmaf(fmaxf(a0 + b1, 0.f), w, acc[0][1]);                 \
            acc[0][2] = fmaf(fmaxf(a0 + b2, 0.f), w, acc[0][2]);                 \
            acc[0][3] = fmaf(fmaxf(a0 + b3, 0.f), w, acc[0][3]);                 \
            acc[1][0] = fmaf(fmaxf(a1 + b0, 0.f), w, acc[1][0]);                 \
            acc[1][1] = fmaf(fmaxf(a1 + b1, 0.f), w, acc[1][1]);                 \
            acc[1][2] = fmaf(fmaxf(a1 + b2, 0.f), w, acc[1][2]);                 \
            acc[1][3] = fmaf(fmaxf(a1 + b3, 0.f), w, acc[1][3]);                 \
            acc[2][0] = fmaf(fmaxf(a2 + b0, 0.f), w, acc[2][0]);                 \
            acc[2][1] = fmaf(fmaxf(a2 + b1, 0.f), w, acc[2][1]);                 \
            acc[2][2] = fmaf(fmaxf(a2 + b2, 0.f), w, acc[2][2]);                 \
            acc[2][3] = fmaf(fmaxf(a2 + b3, 0.f), w, acc[2][3]);                 \
            acc[3][0] = fmaf(fmaxf(a3 + b0, 0.f), w, acc[3][0]);                 \
            acc[3][1] = fmaf(fmaxf(a3 + b1, 0.f), w, acc[3][1]);                 \
            acc[3][2] = fmaf(fmaxf(a3 + b2, 0.f), w, acc[3][2]);                 \
            acc[3][3] = fmaf(fmaxf(a3 + b3, 0.f), w, acc[3][3]);                 \
        }
        EDGE_STEP(x)
        EDGE_STEP(y)
        EDGE_STEP(z)
        EDGE_STEP(w)
#undef EDGE_STEP
    }

    int ibase = bi * TILE;
    int jbase = bj * TILE;
    #pragma unroll
    for (int r = 0; r < 4; r++) {
        int i = ibase + ty + r * 16;
        // linear index of (i,j) in row-major upper triangle (k=1):
        //   m = i*(N-1) - i*(i-1)/2 + (j - i - 1)
        int off = i * (N_NODES - 1) - ((i * (i - 1)) >> 1) - i - 1;
        #pragma unroll
        for (int c = 0; c < 4; c++) {
            int j = jbase + tx + c * 16;
            if (j > i) {
                out[off + j] = sigmoid_fast(acc[r][c] + c0);
            }
        }
    }
}

// =====================================================================
// Launch
// =====================================================================
extern "C" void kernel_launch(void* const* d_in, const int* in_sizes, int n_in,
                              void* d_out, int out_size) {
    const float* clean_features = (const float*)d_in[0];
    const int*   selected_nodes = (const int*)  d_in[1];
    const float* noise          = (const float*)d_in[2];
    const float* gcn1_w         = (const float*)d_in[3];
    const float* gcn1_b         = (const float*)d_in[4];
    const float* gcn2_w         = (const float*)d_in[5];
    const float* gcn2_b         = (const float*)d_in[6];
    const float* gcn3_w         = (const float*)d_in[7];
    const float* gcn3_b         = (const float*)d_in[8];
    const float* ew1            = (const float*)d_in[9];
    const float* eb1            = (const float*)d_in[10];
    const float* ew2            = (const float*)d_in[11];
    const float* eb2            = (const float*)d_in[12];

    float* out = (float*)d_out;
    float* trig_out = out;                    // [2048, 256]
    float* edge_out = out + N_NODES * FDIM;   // [2096128]

    // 1 gcn block + 255 noise blocks (255*8 = 2040 >= 2038 rows)
    merged_kernel<<<256, 1024>>>(clean_features, selected_nodes,
                                 gcn1_w, gcn1_b, gcn2_w, gcn2_b, gcn3_w, gcn3_b,
                                 noise, ew1, eb1, trig_out);

    dim3 grid(N_NODES / TILE, N_NODES / TILE);   // 32 x 32
    edge_kernel<<<grid, 256>>>(ew2, eb2, trig_out, edge_out);
}

// round 9
// speedup vs baseline: 1.3452x; 1.1516x over previous
#include <cuda_runtime.h>
#include <cstdint>

#define N_NODES 2048
#define FDIM 256
#define HID 64
#define TEMPLATE 10
#define RPB 8

// -------- scratch (static device globals; no allocation) --------
__device__ float g_h3[FDIM];
__device__ float g_ha[HID];             // h3 @ ew1[:256] + eb1
__device__ float g_hb[HID];             // h3 @ ew1[256:]
__device__ float g_pa[N_NODES * HID];   // 0.1*noise @ ew1[:256]  (rows 0-9 zero)
__device__ float g_pb[N_NODES * HID];   // 0.1*noise @ ew1[256:]  (rows 0-9 zero)

__device__ __forceinline__ float sigmoid_fast(float x) {
    float t;
    asm("tanh.approx.f32 %0, %1;" : "=f"(t) : "f"(0.5f * x));
    return fmaf(0.5f, t, 0.5f);
}

// =====================================================================
// Merged kernel: block 0 = GCN with smem-staged weights; blocks 1..255 =
// noise GEMM (0.1*noise @ ew1) + trig noise rows. 1024 threads.
// Dynamic smem layout (floats):
//   gcn : w1s 0..16384 | w2s 16384..20480 | w3s 20480..36864 |
//         proto 36864 | red 37120 (4096) | h1 41216 | h2 41280 | h3s 41344
//   noise: tst 0 ([256][9]=2304) | part 2304 ([8][8][128]=8192)
// =====================================================================
#define SMEM_FLOATS 41600
#define SMEM_BYTES  (SMEM_FLOATS * 4)

extern __shared__ float sm[];

__global__ __launch_bounds__(1024) void merged_kernel(
        const float* __restrict__ cf,  const int* __restrict__ sel,
        const float* __restrict__ w1, const float* __restrict__ b1,
        const float* __restrict__ w2, const float* __restrict__ b2,
        const float* __restrict__ w3, const float* __restrict__ b3,
        const float* __restrict__ noise,
        const float* __restrict__ ew1,
        float* __restrict__ trig_out) {
    int t = threadIdx.x;  // 0..1023
    int b = blockIdx.x;

    if (b == 0) {
        // ================= GCN block =================
        float* w1s   = sm;
        float* w2s   = sm + 16384;
        float* w3s   = sm + 20480;
        float* proto = sm + 36864;
        float* red   = sm + 37120;   // 4096 floats, layouts vary per layer
        float* h1    = sm + 41216;
        float* h2    = sm + 41280;
        float* h3s   = sm + 41344;

        // start the critical chain
        int sidx[TEMPLATE];
        #pragma unroll
        for (int q = 0; q < TEMPLATE; q++) sidx[q] = sel[q];

        // stream all weights to smem (coalesced float4, max MLP)
        #pragma unroll
        for (int i = 0; i < 4; i++) {
            int idx = t + i * 1024;
            ((float4*)w1s)[idx] = ((const float4*)w1)[idx];
        }
        ((float4*)w2s)[t] = ((const float4*)w2)[t];
        #pragma unroll
        for (int i = 0; i < 4; i++) {
            int idx = t + i * 1024;
            ((float4*)w3s)[idx] = ((const float4*)w3)[idx];
        }

        // proto = mean of selected rows
        if (t < FDIM) {
            float s = 0.f;
            #pragma unroll
            for (int q = 0; q < TEMPLATE; q++)
                s += cf[(size_t)sidx[q] * FDIM + t];
            proto[t] = s * (1.0f / TEMPLATE);
        }
        __syncthreads();

        int o1 = t & 63, kq1 = t >> 6;   // 16 chunks

        // layer1: 256 -> 64 (16 chunks of 16 k)
        {
            float a0 = 0.f, a1 = 0.f, a2 = 0.f, a3 = 0.f;
            int kb = kq1 * 16;
            #pragma unroll
            for (int kk = 0; kk < 16; kk += 4) {
                a0 = fmaf(proto[kb+kk],   w1s[(kb+kk)  *HID + o1], a0);
                a1 = fmaf(proto[kb+kk+1], w1s[(kb+kk+1)*HID + o1], a1);
                a2 = fmaf(proto[kb+kk+2], w1s[(kb+kk+2)*HID + o1], a2);
                a3 = fmaf(proto[kb+kk+3], w1s[(kb+kk+3)*HID + o1], a3);
            }
            red[kq1 * 64 + o1] = (a0 + a1) + (a2 + a3);
        }
        __syncthreads();
        if (t < HID) {
            float s = b1[t];
            #pragma unroll
            for (int c = 0; c < 16; c++) s += red[c * 64 + t];
            h1[t] = fmaxf(s, 0.f);
        }
        __syncthreads();

        // layer2: 64 -> 64 (16 chunks of 4 k)
        {
            int kb = kq1 * 4;
            float a0 = fmaf(h1[kb],   w2s[(kb)  *HID + o1], 0.f);
            float a1 = fmaf(h1[kb+1], w2s[(kb+1)*HID + o1], 0.f);
            a0 = fmaf(h1[kb+2], w2s[(kb+2)*HID + o1], a0);
            a1 = fmaf(h1[kb+3], w2s[(kb+3)*HID + o1], a1);
            red[kq1 * 64 + o1] = a0 + a1;
        }
        __syncthreads();
        if (t < HID) {
            float s = b2[t];
            #pragma unroll
            for (int c = 0; c < 16; c++) s += red[c * 64 + t];
            h2[t] = fmaxf(s, 0.f);
        }
        __syncthreads();

        // layer3: 64 -> 256 (4 chunks of 16 k)
        {
            int o3 = t & 255, kh3 = t >> 8;
            int kb = kh3 * 16;
            float a0 = 0.f, a1 = 0.f, a2 = 0.f, a3 = 0.f;
            #pragma unroll
            for (int kk = 0; kk < 16; kk += 4) {
                a0 = fmaf(h2[kb+kk],   w3s[(kb+kk)  *FDIM + o3], a0);
                a1 = fmaf(h2[kb+kk+1], w3s[(kb+kk+1)*FDIM + o3], a1);
                a2 = fmaf(h2[kb+kk+2], w3s[(kb+kk+2)*FDIM + o3], a2);
                a3 = fmaf(h2[kb+kk+3], w3s[(kb+kk+3)*FDIM + o3], a3);
            }
            red[kh3 * 256 + o3] = (a0 + a1) + (a2 + a3);
        }
        __syncthreads();
        if (t < FDIM) {
            float a = red[t] + red[256 + t] + red[512 + t] + red[768 + t] + b3[t];
            float v = 1.0f / (1.0f + __expf(-a));
            h3s[t] = v;
            g_h3[t] = v;
            // trig rows 0..9 = h3
            #pragma unroll
            for (int r = 0; r < TEMPLATE; r++)
                trig_out[(size_t)r * FDIM + t] = v;
        }
        // zero pa/pb rows 0..9
        if (t < TEMPLATE * HID) {
            g_pa[t] = 0.f;
            g_pb[t] = 0.f;
        }
        return;
    }

    // ================= noise GEMM blocks =================
    float* tst  = sm;          // [256][9]
    float* part = sm + 2304;   // [8][8][128]
    int r0 = TEMPLATE + (b - 1) * RPB;

    {
        int k = t & 255, g = t >> 8;   // g in 0..3, rows 2g, 2g+1
        #pragma unroll
        for (int rr2 = 0; rr2 < 2; rr2++) {
            int rr = 2 * g + rr2;
            int r = r0 + rr;
            if (r < N_NODES) {
                float v = 0.1f * noise[(size_t)(r - TEMPLATE) * FDIM + k];
                tst[k * 9 + rr] = v;
                trig_out[(size_t)r * FDIM + k] = v;
            } else {
                tst[k * 9 + rr] = 0.f;
            }
        }
    }
    __syncthreads();

    {
        int o = t & 127, c = t >> 7;       // 8 chunks of 32 k
        int half = o >> 6, oc = o & 63;
        const float* w = ew1 + ((size_t)half * FDIM + c * 32) * HID + oc;

        float acc[RPB];
        #pragma unroll
        for (int rr = 0; rr < RPB; rr++) acc[rr] = 0.f;

        #pragma unroll 4
        for (int kk = 0; kk < 32; kk++) {
            int k = c * 32 + kk;
            float wv = w[(size_t)kk * HID];
            #pragma unroll
            for (int rr = 0; rr < RPB; rr++)
                acc[rr] = fmaf(tst[k * 9 + rr], wv, acc[rr]);
        }
        #pragma unroll
        for (int rr = 0; rr < RPB; rr++)
            part[(c * 8 + rr) * 128 + o] = acc[rr];
    }
    __syncthreads();

    {
        int rr = t >> 7, oo = t & 127;
        int r = r0 + rr;
        if (r < N_NODES) {
            float s = 0.f;
            #pragma unroll
            for (int c = 0; c < 8; c++) s += part[(c * 8 + rr) * 128 + oo];
            int half = oo >> 6, oc = oo & 63;
            if (half == 0) g_pa[(size_t)r * HID + oc] = s;
            else           g_pb[(size_t)r * HID + oc] = s;
        }
    }
}

// =====================================================================
// gemv_hab: ha = h3 @ ew1[:256] + eb1 ; hb = h3 @ ew1[256:]
// 128 blocks x 256 threads; ew1 read spread over many SMs.
// =====================================================================
__global__ __launch_bounds__(256) void gemv_hab(
        const float* __restrict__ ew1, const float* __restrict__ eb1) {
    __shared__ float red[8];
    int b = blockIdx.x;            // 0..127
    int half = b >> 6, oc = b & 63;
    int t = threadIdx.x;           // 0..255

    float v = g_h3[t] * ew1[((size_t)(half * FDIM + t)) * HID + oc];
    #pragma unroll
    for (int off = 16; off > 0; off >>= 1)
        v += __shfl_xor_sync(0xffffffffu, v, off);
    if ((t & 31) == 0) red[t >> 5] = v;
    __syncthreads();
    if (t == 0) {
        float s = red[0] + red[1] + red[2] + red[3] +
                  red[4] + red[5] + red[6] + red[7];
        if (half == 0) g_ha[oc] = s + eb1[oc];
        else           g_hb[oc] = s;
    }
}

// =====================================================================
// Edge kernel: 1D grid. Blocks 0..527 = upper-tri 64x64 tiles;
// blocks 528..543 = trig fixup (trig[10:] += h3, float4).
// =====================================================================
#define TILE 64
#define PADK 68
#define NT   (N_NODES / TILE)         // 32
#define NTILES (NT * (NT + 1) / 2)    // 528
#define NFIX 16

__global__ __launch_bounds__(256) void edge_kernel(const float* __restrict__ ew2,
                                                   const float* __restrict__ eb2,
                                                   float* __restrict__ trig_out,
                                                   float* __restrict__ out) {
    int m = blockIdx.x;
    int tid = threadIdx.x;

    if (m >= NTILES) {
        // -------- trig fixup: trig[10:][:] += h3 (float4) --------
        int f = m - NTILES;                                  // 0..15
        const int total4 = (N_NODES - TEMPLATE) * FDIM / 4;  // 130432
        const int per = (total4 + NFIX - 1) / NFIX;          // 8152
        int s = f * per;
        int e = s + per; if (e > total4) e = total4;
        float4* base = (float4*)(trig_out + (size_t)TEMPLATE * FDIM);
        for (int i = s + tid; i < e; i += 256) {
            int c4 = i & 63;                                 // 64 float4 per row
            float4 h = __ldg((const float4*)&g_h3[c4 * 4]);
            float4 v = base[i];
            v.x += h.x; v.y += h.y; v.z += h.z; v.w += h.w;
            base[i] = v;
        }
        return;
    }

    // decode (bi, bj) with bj >= bi from m
    int bi = (int)(32.5f - sqrtf(32.5f * 32.5f - 2.0f * (float)m));
    while (bi * NT - ((bi * (bi - 1)) >> 1) > m) bi--;
    while ((bi + 1) * NT - (((bi + 1) * bi) >> 1) <= m) bi++;
    int bj = bi + (m - (bi * NT - ((bi * (bi - 1)) >> 1)));

    __shared__ float pa_s[TILE][PADK];
    __shared__ float pb_s[TILE][PADK];
    __shared__ float w2_s[HID];

    const float* paG = g_pa + bi * TILE * HID;
    const float* pbG = g_pb + bj * TILE * HID;
    #pragma unroll
    for (int it = 0; it < 4; it++) {
        int idx = tid + it * 256;
        int row = idx >> 4;
        int kq  = (idx & 15) << 2;
        float4 ha4 = __ldg((const float4*)&g_ha[kq]);
        float4 hb4 = __ldg((const float4*)&g_hb[kq]);
        float4 va = *(const float4*)(paG + row * HID + kq);
        pa_s[row][kq]   = va.x + ha4.x;
        pa_s[row][kq+1] = va.y + ha4.y;
        pa_s[row][kq+2] = va.z + ha4.z;
        pa_s[row][kq+3] = va.w + ha4.w;
        float4 vb = *(const float4*)(pbG + row * HID + kq);
        pb_s[row][kq]   = vb.x + hb4.x;
        pb_s[row][kq+1] = vb.y + hb4.y;
        pb_s[row][kq+2] = vb.z + hb4.z;
        pb_s[row][kq+3] = vb.w + hb4.w;
    }
    if (tid < HID) w2_s[tid] = ew2[tid];
    float c0 = eb2[0];
    __syncthreads();

    int tx = tid & 15;   // j-direction
    int ty = tid >> 4;   // i-direction

    float acc[4][4];
    #pragma unroll
    for (int r = 0; r < 4; r++)
        #pragma unroll
        for (int c = 0; c < 4; c++) acc[r][c] = 0.f;

    #pragma unroll 4
    for (int kq = 0; kq < HID; kq += 4) {
        float4 w4 = *(const float4*)&w2_s[kq];
        float4 A0 = *(const float4*)&pa_s[ty     ][kq];
        float4 A1 = *(const float4*)&pa_s[ty + 16][kq];
        float4 A2 = *(const float4*)&pa_s[ty + 32][kq];
        float4 A3 = *(const float4*)&pa_s[ty + 48][kq];
        float4 B0 = *(const float4*)&pb_s[tx     ][kq];
        float4 B1 = *(const float4*)&pb_s[tx + 16][kq];
        float4 B2 = *(const float4*)&pb_s[tx + 32][kq];
        float4 B3 = *(const float4*)&pb_s[tx + 48][kq];

#define EDGE_STEP(COMP)                                                          \
        {                                                                        \
            float a0 = A0.COMP, a1 = A1.COMP, a2 = A2.COMP, a3 = A3.COMP;        \
            float b0 = B0.COMP, b1 = B1.COMP, b2 = B2.COMP, b3 = B3.COMP;        \
            float w  = w4.COMP;                                                  \
            acc[0][0] = fmaf(fmaxf(a0 + b0, 0.f), w, acc[0][0]);                 \
            acc[0][1] = fmaf(fmaxf(a0 + b1, 0.f), w, acc[0][1]);                 \
            acc[0][2] = fmaf(fmaxf(a0 + b2, 0.f), w, acc[0][2]);                 \
            acc[0][3] = fmaf(fmaxf(a0 + b3, 0.f), w, acc[0][3]);                 \
            acc[1][0] = fmaf(fmaxf(a1 + b0, 0.f), w, acc[1][0]);                 \
            acc[1][1] = fmaf(fmaxf(a1 + b1, 0.f), w, acc[1][1]);                 \
            acc[1][2] = fmaf(fmaxf(a1 + b2, 0.f), w, acc[1][2]);                 \
            acc[1][3] = fmaf(fmaxf(a1 + b3, 0.f), w, acc[1][3]);                 \
            acc[2][0] = fmaf(fmaxf(a2 + b0, 0.f), w, acc[2][0]);                 \
            acc[2][1] = fmaf(fmaxf(a2 + b1, 0.f), w, acc[2][1]);                 \
            acc[2][2] = fmaf(fmaxf(a2 + b2, 0.f), w, acc[2][2]);                 \
            acc[2][3] = fmaf(fmaxf(a2 + b3, 0.f), w, acc[2][3]);                 \
            acc[3][0] = fmaf(fmaxf(a3 + b0, 0.f), w, acc[3][0]);                 \
            acc[3][1] = fmaf(fmaxf(a3 + b1, 0.f), w, acc[3][1]);                 \
            acc[3][2] = fmaf(fmaxf(a3 + b2, 0.f), w, acc[3][2]);                 \
            acc[3][3] = fmaf(fmaxf(a3 + b3, 0.f), w, acc[3][3]);                 \
        }
        EDGE_STEP(x)
        EDGE_STEP(y)
        EDGE_STEP(z)
        EDGE_STEP(w)
#undef EDGE_STEP
    }

    int ibase = bi * TILE;
    int jbase = bj * TILE;
    #pragma unroll
    for (int r = 0; r < 4; r++) {
        int i = ibase + ty + r * 16;
        int off = i * (N_NODES - 1) - ((i * (i - 1)) >> 1) - i - 1;
        #pragma unroll
        for (int c = 0; c < 4; c++) {
            int j = jbase + tx + c * 16;
            if (j > i) {
                out[off + j] = sigmoid_fast(acc[r][c] + c0);
            }
        }
    }
}

// =====================================================================
// Launch
// =====================================================================
extern "C" void kernel_launch(void* const* d_in, const int* in_sizes, int n_in,
                              void* d_out, int out_size) {
    const float* clean_features = (const float*)d_in[0];
    const int*   selected_nodes = (const int*)  d_in[1];
    const float* noise          = (const float*)d_in[2];
    const float* gcn1_w         = (const float*)d_in[3];
    const float* gcn1_b         = (const float*)d_in[4];
    const float* gcn2_w         = (const float*)d_in[5];
    const float* gcn2_b         = (const float*)d_in[6];
    const float* gcn3_w         = (const float*)d_in[7];
    const float* gcn3_b         = (const float*)d_in[8];
    const float* ew1            = (const float*)d_in[9];
    const float* eb1            = (const float*)d_in[10];
    const float* ew2            = (const float*)d_in[11];
    const float* eb2            = (const float*)d_in[12];

    float* out = (float*)d_out;
    float* trig_out = out;                    // [2048, 256]
    float* edge_out = out + N_NODES * FDIM;   // [2096128]

    // idempotent, called every launch (no static guards per harness rules)
    cudaFuncSetAttribute(merged_kernel,
                         cudaFuncAttributeMaxDynamicSharedMemorySize,
                         SMEM_BYTES);

    merged_kernel<<<256, 1024, SMEM_BYTES>>>(
        clean_features, selected_nodes,
        gcn1_w, gcn1_b, gcn2_w, gcn2_b, gcn3_w, gcn3_b,
        noise, ew1, trig_out);

    gemv_hab<<<128, 256>>>(ew1, eb1);

    edge_kernel<<<NTILES + NFIX, 256>>>(ew2, eb2, trig_out, edge_out);
}

// round 10
// speedup vs baseline: 1.3949x; 1.0369x over previous
#include <cuda_runtime.h>
#include <cstdint>

#define N_NODES 2048
#define FDIM 256
#define HID 64
#define TEMPLATE 10
#define RPB 16

// -------- scratch (static device globals; no allocation) --------
__device__ float g_h3[FDIM];
__device__ float g_ha[HID];             // h3 @ ew1[:256] + eb1
__device__ float g_hb[HID];             // h3 @ ew1[256:]
__device__ float g_pa[N_NODES * HID];   // 0.1*noise @ ew1[:256]  (rows 0-9 zero)
__device__ float g_pb[N_NODES * HID];   // 0.1*noise @ ew1[256:]  (rows 0-9 zero)

__device__ __forceinline__ float sigmoid_fast(float x) {
    float t;
    asm("tanh.approx.f32 %0, %1;" : "=f"(t) : "f"(0.5f * x));
    return fmaf(0.5f, t, 0.5f);
}

// =====================================================================
// Merged kernel: block 0 = GCN with smem-staged weights; blocks 1..128 =
// noise GEMM (0.1*noise @ ew1), 16 rows each -> 129 blocks = ONE wave.
// Dynamic smem layout (floats):
//   gcn : w1s 0..16384 | w2s 16384..20480 | w3s 20480..36864 |
//         proto 36864 | red 37120 (4096) | h1 41216 | h2 41280 | h3s 41344
//   noise: tst 0 ([256][20]=5120) | part 5120 ([8][16][128]=16384)
// =====================================================================
#define SMEM_FLOATS 41600
#define SMEM_BYTES  (SMEM_FLOATS * 4)
#define TSTRIDE 20   // 80B row: 16B-aligned for LDS.128, mild STS conflicts

extern __shared__ float sm[];

__global__ __launch_bounds__(1024) void merged_kernel(
        const float* __restrict__ cf,  const int* __restrict__ sel,
        const float* __restrict__ w1, const float* __restrict__ b1,
        const float* __restrict__ w2, const float* __restrict__ b2,
        const float* __restrict__ w3, const float* __restrict__ b3,
        const float* __restrict__ noise,
        const float* __restrict__ ew1,
        float* __restrict__ trig_out) {
    int t = threadIdx.x;  // 0..1023
    int b = blockIdx.x;

    if (b == 0) {
        // ================= GCN block =================
        float* w1s   = sm;
        float* w2s   = sm + 16384;
        float* w3s   = sm + 20480;
        float* proto = sm + 36864;
        float* red   = sm + 37120;   // 4096 floats, layouts vary per layer
        float* h1    = sm + 41216;
        float* h2    = sm + 41280;
        float* h3s   = sm + 41344;

        // start the critical chain
        int sidx[TEMPLATE];
        #pragma unroll
        for (int q = 0; q < TEMPLATE; q++) sidx[q] = sel[q];

        // stream all weights to smem (coalesced float4, max MLP)
        #pragma unroll
        for (int i = 0; i < 4; i++) {
            int idx = t + i * 1024;
            ((float4*)w1s)[idx] = ((const float4*)w1)[idx];
        }
        ((float4*)w2s)[t] = ((const float4*)w2)[t];
        #pragma unroll
        for (int i = 0; i < 4; i++) {
            int idx = t + i * 1024;
            ((float4*)w3s)[idx] = ((const float4*)w3)[idx];
        }

        // proto = mean of selected rows
        if (t < FDIM) {
            float s = 0.f;
            #pragma unroll
            for (int q = 0; q < TEMPLATE; q++)
                s += cf[(size_t)sidx[q] * FDIM + t];
            proto[t] = s * (1.0f / TEMPLATE);
        }
        __syncthreads();

        int o1 = t & 63, kq1 = t >> 6;   // 16 chunks

        // layer1: 256 -> 64 (16 chunks of 16 k)
        {
            float a0 = 0.f, a1 = 0.f, a2 = 0.f, a3 = 0.f;
            int kb = kq1 * 16;
            #pragma unroll
            for (int kk = 0; kk < 16; kk += 4) {
                a0 = fmaf(proto[kb+kk],   w1s[(kb+kk)  *HID + o1], a0);
                a1 = fmaf(proto[kb+kk+1], w1s[(kb+kk+1)*HID + o1], a1);
                a2 = fmaf(proto[kb+kk+2], w1s[(kb+kk+2)*HID + o1], a2);
                a3 = fmaf(proto[kb+kk+3], w1s[(kb+kk+3)*HID + o1], a3);
            }
            red[kq1 * 64 + o1] = (a0 + a1) + (a2 + a3);
        }
        __syncthreads();
        if (t < HID) {
            float s = b1[t];
            #pragma unroll
            for (int c = 0; c < 16; c++) s += red[c * 64 + t];
            h1[t] = fmaxf(s, 0.f);
        }
        __syncthreads();

        // layer2: 64 -> 64 (16 chunks of 4 k)
        {
            int kb = kq1 * 4;
            float a0 = fmaf(h1[kb],   w2s[(kb)  *HID + o1], 0.f);
            float a1 = fmaf(h1[kb+1], w2s[(kb+1)*HID + o1], 0.f);
            a0 = fmaf(h1[kb+2], w2s[(kb+2)*HID + o1], a0);
            a1 = fmaf(h1[kb+3], w2s[(kb+3)*HID + o1], a1);
            red[kq1 * 64 + o1] = a0 + a1;
        }
        __syncthreads();
        if (t < HID) {
            float s = b2[t];
            #pragma unroll
            for (int c = 0; c < 16; c++) s += red[c * 64 + t];
            h2[t] = fmaxf(s, 0.f);
        }
        __syncthreads();

        // layer3: 64 -> 256 (4 chunks of 16 k)
        {
            int o3 = t & 255, kh3 = t >> 8;
            int kb = kh3 * 16;
            float a0 = 0.f, a1 = 0.f, a2 = 0.f, a3 = 0.f;
            #pragma unroll
            for (int kk = 0; kk < 16; kk += 4) {
                a0 = fmaf(h2[kb+kk],   w3s[(kb+kk)  *FDIM + o3], a0);
                a1 = fmaf(h2[kb+kk+1], w3s[(kb+kk+1)*FDIM + o3], a1);
                a2 = fmaf(h2[kb+kk+2], w3s[(kb+kk+2)*FDIM + o3], a2);
                a3 = fmaf(h2[kb+kk+3], w3s[(kb+kk+3)*FDIM + o3], a3);
            }
            red[kh3 * 256 + o3] = (a0 + a1) + (a2 + a3);
        }
        __syncthreads();
        if (t < FDIM) {
            float a = red[t] + red[256 + t] + red[512 + t] + red[768 + t] + b3[t];
            float v = 1.0f / (1.0f + __expf(-a));
            h3s[t] = v;
            g_h3[t] = v;
            // trig rows 0..9 = h3
            #pragma unroll
            for (int r = 0; r < TEMPLATE; r++)
                trig_out[(size_t)r * FDIM + t] = v;
        }
        // zero pa/pb rows 0..9
        if (t < TEMPLATE * HID) {
            g_pa[t] = 0.f;
            g_pb[t] = 0.f;
        }
        return;
    }

    // ================= noise GEMM blocks (16 rows each) =================
    float* tst  = sm;                       // [256][TSTRIDE]
    float* part = sm + FDIM * TSTRIDE;      // [8][16][128]
    int r0 = TEMPLATE + (b - 1) * RPB;

    // prologue: load 0.1*noise (transposed into tst), write trig noise rows
    {
        int k = t & 255, g = t >> 8;        // g in 0..3 -> rows 4g..4g+3
        #pragma unroll
        for (int rr2 = 0; rr2 < 4; rr2++) {
            int rr = 4 * g + rr2;
            int r = r0 + rr;
            if (r < N_NODES) {
                float v = 0.1f * noise[(size_t)(r - TEMPLATE) * FDIM + k];
                tst[k * TSTRIDE + rr] = v;
                trig_out[(size_t)r * FDIM + k] = v;
            } else {
                tst[k * TSTRIDE + rr] = 0.f;
            }
        }
    }
    __syncthreads();

    // GEMM: o = t&127 (half 0 -> pa col, half 1 -> pb col), c = t>>7
    // 8 k-chunks of 32; 16 accumulators (rows) per thread.
    {
        int o = t & 127, c = t >> 7;
        int half = o >> 6, oc = o & 63;
        const float* w = ew1 + ((size_t)half * FDIM + c * 32) * HID + oc;
        const float* tb = tst + (c * 32) * TSTRIDE;

        float acc[RPB];
        #pragma unroll
        for (int rr = 0; rr < RPB; rr++) acc[rr] = 0.f;

        #pragma unroll 4
        for (int kk = 0; kk < 32; kk++) {
            float wv = w[(size_t)kk * HID];
            const float* row = tb + kk * TSTRIDE;
            float4 rA = *(const float4*)(row);       // rows 0..3   (broadcast)
            float4 rB = *(const float4*)(row + 4);   // rows 4..7
            float4 rC = *(const float4*)(row + 8);   // rows 8..11
            float4 rD = *(const float4*)(row + 12);  // rows 12..15
            acc[0]  = fmaf(rA.x, wv, acc[0]);
            acc[1]  = fmaf(rA.y, wv, acc[1]);
            acc[2]  = fmaf(rA.z, wv, acc[2]);
            acc[3]  = fmaf(rA.w, wv, acc[3]);
            acc[4]  = fmaf(rB.x, wv, acc[4]);
            acc[5]  = fmaf(rB.y, wv, acc[5]);
            acc[6]  = fmaf(rB.z, wv, acc[6]);
            acc[7]  = fmaf(rB.w, wv, acc[7]);
            acc[8]  = fmaf(rC.x, wv, acc[8]);
            acc[9]  = fmaf(rC.y, wv, acc[9]);
            acc[10] = fmaf(rC.z, wv, acc[10]);
            acc[11] = fmaf(rC.w, wv, acc[11]);
            acc[12] = fmaf(rD.x, wv, acc[12]);
            acc[13] = fmaf(rD.y, wv, acc[13]);
            acc[14] = fmaf(rD.z, wv, acc[14]);
            acc[15] = fmaf(rD.w, wv, acc[15]);
        }
        #pragma unroll
        for (int rr = 0; rr < RPB; rr++)
            part[(c * RPB + rr) * 128 + o] = acc[rr];
    }
    __syncthreads();

    // reduce 8 chunks; 2048 outputs over 1024 threads (2 each)
    {
        #pragma unroll
        for (int u = 0; u < 2; u++) {
            int idx = t + u * 1024;
            int rr = idx >> 7, oo = idx & 127;
            int r = r0 + rr;
            if (r < N_NODES) {
                float s = 0.f;
                #pragma unroll
                for (int c = 0; c < 8; c++)
                    s += part[(c * RPB + rr) * 128 + oo];
                int half = oo >> 6, oc = oo & 63;
                if (half == 0) g_pa[(size_t)r * HID + oc] = s;
                else           g_pb[(size_t)r * HID + oc] = s;
            }
        }
    }
}

// =====================================================================
// gemv_hab: ha = h3 @ ew1[:256] + eb1 ; hb = h3 @ ew1[256:]
// 128 blocks x 256 threads.
// =====================================================================
__global__ __launch_bounds__(256) void gemv_hab(
        const float* __restrict__ ew1, const float* __restrict__ eb1) {
    __shared__ float red[8];
    int b = blockIdx.x;            // 0..127
    int half = b >> 6, oc = b & 63;
    int t = threadIdx.x;           // 0..255

    float v = g_h3[t] * ew1[((size_t)(half * FDIM + t)) * HID + oc];
    #pragma unroll
    for (int off = 16; off > 0; off >>= 1)
        v += __shfl_xor_sync(0xffffffffu, v, off);
    if ((t & 31) == 0) red[t >> 5] = v;
    __syncthreads();
    if (t == 0) {
        float s = red[0] + red[1] + red[2] + red[3] +
                  red[4] + red[5] + red[6] + red[7];
        if (half == 0) g_ha[oc] = s + eb1[oc];
        else           g_hb[oc] = s;
    }
}

// =====================================================================
// Edge kernel: 1D grid. Blocks 0..527 = upper-tri 64x64 tiles;
// blocks 528..543 = trig fixup (trig[10:] += h3, float4).
// =====================================================================
#define TILE 64
#define PADK 68
#define NT   (N_NODES / TILE)         // 32
#define NTILES (NT * (NT + 1) / 2)    // 528
#define NFIX 16

__global__ __launch_bounds__(256) void edge_kernel(const float* __restrict__ ew2,
                                                   const float* __restrict__ eb2,
                                                   float* __restrict__ trig_out,
                                                   float* __restrict__ out) {
    int m = blockIdx.x;
    int tid = threadIdx.x;

    if (m >= NTILES) {
        // -------- trig fixup: trig[10:][:] += h3 (float4) --------
        int f = m - NTILES;                                  // 0..15
        const int total4 = (N_NODES - TEMPLATE) * FDIM / 4;  // 130432
        const int per = (total4 + NFIX - 1) / NFIX;          // 8152
        int s = f * per;
        int e = s + per; if (e > total4) e = total4;
        float4* base = (float4*)(trig_out + (size_t)TEMPLATE * FDIM);
        for (int i = s + tid; i < e; i += 256) {
            int c4 = i & 63;                                 // 64 float4 per row
            float4 h = __ldg((const float4*)&g_h3[c4 * 4]);
            float4 v = base[i];
            v.x += h.x; v.y += h.y; v.z += h.z; v.w += h.w;
            base[i] = v;
        }
        return;
    }

    // decode (bi, bj) with bj >= bi from m
    int bi = (int)(32.5f - sqrtf(32.5f * 32.5f - 2.0f * (float)m));
    while (bi * NT - ((bi * (bi - 1)) >> 1) > m) bi--;
    while ((bi + 1) * NT - (((bi + 1) * bi) >> 1) <= m) bi++;
    int bj = bi + (m - (bi * NT - ((bi * (bi - 1)) >> 1)));

    __shared__ float pa_s[TILE][PADK];
    __shared__ float pb_s[TILE][PADK];
    __shared__ float w2_s[HID];

    const float* paG = g_pa + bi * TILE * HID;
    const float* pbG = g_pb + bj * TILE * HID;
    #pragma unroll
    for (int it = 0; it < 4; it++) {
        int idx = tid + it * 256;
        int row = idx >> 4;
        int kq  = (idx & 15) << 2;
        float4 ha4 = __ldg((const float4*)&g_ha[kq]);
        float4 hb4 = __ldg((const float4*)&g_hb[kq]);
        float4 va = *(const float4*)(paG + row * HID + kq);
        pa_s[row][kq]   = va.x + ha4.x;
        pa_s[row][kq+1] = va.y + ha4.y;
        pa_s[row][kq+2] = va.z + ha4.z;
        pa_s[row][kq+3] = va.w + ha4.w;
        float4 vb = *(const float4*)(pbG + row * HID + kq);
        pb_s[row][kq]   = vb.x + hb4.x;
        pb_s[row][kq+1] = vb.y + hb4.y;
        pb_s[row][kq+2] = vb.z + hb4.z;
        pb_s[row][kq+3] = vb.w + hb4.w;
    }
    if (tid < HID) w2_s[tid] = ew2[tid];
    float c0 = eb2[0];
    __syncthreads();

    int tx = tid & 15;   // j-direction
    int ty = tid >> 4;   // i-direction

    float acc[4][4];
    #pragma unroll
    for (int r = 0; r < 4; r++)
        #pragma unroll
        for (int c = 0; c < 4; c++) acc[r][c] = 0.f;

    #pragma unroll 4
    for (int kq = 0; kq < HID; kq += 4) {
        float4 w4 = *(const float4*)&w2_s[kq];
        float4 A0 = *(const float4*)&pa_s[ty     ][kq];
        float4 A1 = *(const float4*)&pa_s[ty + 16][kq];
        float4 A2 = *(const float4*)&pa_s[ty + 32][kq];
        float4 A3 = *(const float4*)&pa_s[ty + 48][kq];
        float4 B0 = *(const float4*)&pb_s[tx     ][kq];
        float4 B1 = *(const float4*)&pb_s[tx + 16][kq];
        float4 B2 = *(const float4*)&pb_s[tx + 32][kq];
        float4 B3 = *(const float4*)&pb_s[tx + 48][kq];

#define EDGE_STEP(COMP)                                                          \
        {                                                                        \
            float a0 = A0.COMP, a1 = A1.COMP, a2 = A2.COMP, a3 = A3.COMP;        \
            float b0 = B0.COMP, b1 = B1.COMP, b2 = B2.COMP, b3 = B3.COMP;        \
            float w  = w4.COMP;                                                  \
            acc[0][0] = fmaf(fmaxf(a0 + b0, 0.f), w, acc[0][0]);                 \
            acc[0][1] = fmaf(fmaxf(a0 + b1, 0.f), w, acc[0][1]);                 \
            acc[0][2] = fmaf(fmaxf(a0 + b2, 0.f), w, acc[0][2]);                 \
            acc[0][3] = fmaf(fmaxf(a0 + b3, 0.f), w, acc[0][3]);                 \
            acc[1][0] = fmaf(fmaxf(a1 + b0, 0.f), w, acc[1][0]);                 \
            acc[1][1] = fmaf(fmaxf(a1 + b1, 0.f), w, acc[1][1]);                 \
            acc[1][2] = fmaf(fmaxf(a1 + b2, 0.f), w, acc[1][2]);                 \
            acc[1][3] = fmaf(fmaxf(a1 + b3, 0.f), w, acc[1][3]);                 \
            acc[2][0] = fmaf(fmaxf(a2 + b0, 0.f), w, acc[2][0]);                 \
            acc[2][1] = fmaf(fmaxf(a2 + b1, 0.f), w, acc[2][1]);                 \
            acc[2][2] = fmaf(fmaxf(a2 + b2, 0.f), w, acc[2][2]);                 \
            acc[2][3] = fmaf(fmaxf(a2 + b3, 0.f), w, acc[2][3]);                 \
            acc[3][0] = fmaf(fmaxf(a3 + b0, 0.f), w, acc[3][0]);                 \
            acc[3][1] = fmaf(fmaxf(a3 + b1, 0.f), w, acc[3][1]);                 \
            acc[3][2] = fmaf(fmaxf(a3 + b2, 0.f), w, acc[3][2]);                 \
            acc[3][3] = fmaf(fmaxf(a3 + b3, 0.f), w, acc[3][3]);                 \
        }
        EDGE_STEP(x)
        EDGE_STEP(y)
        EDGE_STEP(z)
        EDGE_STEP(w)
#undef EDGE_STEP
    }

    int ibase = bi * TILE;
    int jbase = bj * TILE;
    #pragma unroll
    for (int r = 0; r < 4; r++) {
        int i = ibase + ty + r * 16;
        int off = i * (N_NODES - 1) - ((i * (i - 1)) >> 1) - i - 1;
        #pragma unroll
        for (int c = 0; c < 4; c++) {
            int j = jbase + tx + c * 16;
            if (j > i) {
                out[off + j] = sigmoid_fast(acc[r][c] + c0);
            }
        }
    }
}

// =====================================================================
// Launch
// =====================================================================
extern "C" void kernel_launch(void* const* d_in, const int* in_sizes, int n_in,
                              void* d_out, int out_size) {
    const float* clean_features = (const float*)d_in[0];
    const int*   selected_nodes = (const int*)  d_in[1];
    const float* noise          = (const float*)d_in[2];
    const float* gcn1_w         = (const float*)d_in[3];
    const float* gcn1_b         = (const float*)d_in[4];
    const float* gcn2_w         = (const float*)d_in[5];
    const float* gcn2_b         = (const float*)d_in[6];
    const float* gcn3_w         = (const float*)d_in[7];
    const float* gcn3_b         = (const float*)d_in[8];
    const float* ew1            = (const float*)d_in[9];
    const float* eb1            = (const float*)d_in[10];
    const float* ew2            = (const float*)d_in[11];
    const float* eb2            = (const float*)d_in[12];

    float* out = (float*)d_out;
    float* trig_out = out;                    // [2048, 256]
    float* edge_out = out + N_NODES * FDIM;   // [2096128]

    // idempotent, called every launch (no static guards per harness rules)
    cudaFuncSetAttribute(merged_kernel,
                         cudaFuncAttributeMaxDynamicSharedMemorySize,
                         SMEM_BYTES);

    // 1 gcn block + 128 noise blocks (128*16 = 2048 >= 2038 rows) = one wave
    merged_kernel<<<129, 1024, SMEM_BYTES>>>(
        clean_features, selected_nodes,
        gcn1_w, gcn1_b, gcn2_w, gcn2_b, gcn3_w, gcn3_b,
        noise, ew1, trig_out);

    gemv_hab<<<128, 256>>>(ew1, eb1);

    edge_kernel<<<NTILES + NFIX, 256>>>(ew2, eb2, trig_out, edge_out);
}

// round 11
// speedup vs baseline: 1.4109x; 1.0115x over previous
#include <cuda_runtime.h>
#include <cstdint>

#define N_NODES 2048
#define FDIM 256
#define HID 64
#define TEMPLATE 10
#define RPB 16

// -------- scratch (static device globals; no allocation) --------
__device__ float g_h3[FDIM];
__device__ float g_ha[HID];             // h3 @ ew1[:256] + eb1
__device__ float g_hb[HID];             // h3 @ ew1[256:]
__device__ float g_pa[N_NODES * HID];   // 0.1*noise @ ew1[:256]  (rows 0-9 zero)
__device__ float g_pb[N_NODES * HID];   // 0.1*noise @ ew1[256:]  (rows 0-9 zero)

__device__ __forceinline__ float sigmoid_fast(float x) {
    float t;
    asm("tanh.approx.f32 %0, %1;" : "=f"(t) : "f"(0.5f * x));
    return fmaf(0.5f, t, 0.5f);
}

// =====================================================================
// Merged kernel: block 0 = GCN with smem-staged weights; blocks 1..128 =
// noise GEMM (0.1*noise @ ew1), 16 rows each -> 129 blocks = ONE wave.
// Dynamic smem layout (floats):
//   gcn : w1s 0..16384 | w2s 16384..20480 | w3s 20480..36864 |
//         proto 36864 | red 37120 (4096) | h1 41216 | h2 41280 | h3s 41344
//   noise: tst 0 ([256][20]=5120) | part 5120 ([8][16][128]=16384)
// =====================================================================
#define SMEM_FLOATS 41600
#define SMEM_BYTES  (SMEM_FLOATS * 4)
#define TSTRIDE 20   // 80B row: 16B-aligned for LDS.128

extern __shared__ float sm[];

__global__ __launch_bounds__(1024) void merged_kernel(
        const float* __restrict__ cf,  const int* __restrict__ sel,
        const float* __restrict__ w1, const float* __restrict__ b1,
        const float* __restrict__ w2, const float* __restrict__ b2,
        const float* __restrict__ w3, const float* __restrict__ b3,
        const float* __restrict__ noise,
        const float* __restrict__ ew1,
        float* __restrict__ trig_out) {
    int t = threadIdx.x;  // 0..1023
    int b = blockIdx.x;

    if (b == 0) {
        // ================= GCN block =================
        float* w1s   = sm;
        float* w2s   = sm + 16384;
        float* w3s   = sm + 20480;
        float* proto = sm + 36864;
        float* red   = sm + 37120;   // 4096 floats, layouts vary per layer
        float* h1    = sm + 41216;
        float* h2    = sm + 41280;
        float* h3s   = sm + 41344;

        // start the critical chain
        int sidx[TEMPLATE];
        #pragma unroll
        for (int q = 0; q < TEMPLATE; q++) sidx[q] = sel[q];

        // stream all weights to smem (coalesced float4, max MLP)
        #pragma unroll
        for (int i = 0; i < 4; i++) {
            int idx = t + i * 1024;
            ((float4*)w1s)[idx] = ((const float4*)w1)[idx];
        }
        ((float4*)w2s)[t] = ((const float4*)w2)[t];
        #pragma unroll
        for (int i = 0; i < 4; i++) {
            int idx = t + i * 1024;
            ((float4*)w3s)[idx] = ((const float4*)w3)[idx];
        }

        // proto = mean of selected rows
        if (t < FDIM) {
            float s = 0.f;
            #pragma unroll
            for (int q = 0; q < TEMPLATE; q++)
                s += cf[(size_t)sidx[q] * FDIM + t];
            proto[t] = s * (1.0f / TEMPLATE);
        }
        __syncthreads();

        int o1 = t & 63, kq1 = t >> 6;   // 16 chunks

        // layer1: 256 -> 64 (16 chunks of 16 k)
        {
            float a0 = 0.f, a1 = 0.f, a2 = 0.f, a3 = 0.f;
            int kb = kq1 * 16;
            #pragma unroll
            for (int kk = 0; kk < 16; kk += 4) {
                a0 = fmaf(proto[kb+kk],   w1s[(kb+kk)  *HID + o1], a0);
                a1 = fmaf(proto[kb+kk+1], w1s[(kb+kk+1)*HID + o1], a1);
                a2 = fmaf(proto[kb+kk+2], w1s[(kb+kk+2)*HID + o1], a2);
                a3 = fmaf(proto[kb+kk+3], w1s[(kb+kk+3)*HID + o1], a3);
            }
            red[kq1 * 64 + o1] = (a0 + a1) + (a2 + a3);
        }
        __syncthreads();
        if (t < HID) {
            float s = b1[t];
            #pragma unroll
            for (int c = 0; c < 16; c++) s += red[c * 64 + t];
            h1[t] = fmaxf(s, 0.f);
        }
        __syncthreads();

        // layer2: 64 -> 64 (16 chunks of 4 k)
        {
            int kb = kq1 * 4;
            float a0 = fmaf(h1[kb],   w2s[(kb)  *HID + o1], 0.f);
            float a1 = fmaf(h1[kb+1], w2s[(kb+1)*HID + o1], 0.f);
            a0 = fmaf(h1[kb+2], w2s[(kb+2)*HID + o1], a0);
            a1 = fmaf(h1[kb+3], w2s[(kb+3)*HID + o1], a1);
            red[kq1 * 64 + o1] = a0 + a1;
        }
        __syncthreads();
        if (t < HID) {
            float s = b2[t];
            #pragma unroll
            for (int c = 0; c < 16; c++) s += red[c * 64 + t];
            h2[t] = fmaxf(s, 0.f);
        }
        __syncthreads();

        // layer3: 64 -> 256 (4 chunks of 16 k)
        {
            int o3 = t & 255, kh3 = t >> 8;
            int kb = kh3 * 16;
            float a0 = 0.f, a1 = 0.f, a2 = 0.f, a3 = 0.f;
            #pragma unroll
            for (int kk = 0; kk < 16; kk += 4) {
                a0 = fmaf(h2[kb+kk],   w3s[(kb+kk)  *FDIM + o3], a0);
                a1 = fmaf(h2[kb+kk+1], w3s[(kb+kk+1)*FDIM + o3], a1);
                a2 = fmaf(h2[kb+kk+2], w3s[(kb+kk+2)*FDIM + o3], a2);
                a3 = fmaf(h2[kb+kk+3], w3s[(kb+kk+3)*FDIM + o3], a3);
            }
            red[kh3 * 256 + o3] = (a0 + a1) + (a2 + a3);
        }
        __syncthreads();
        if (t < FDIM) {
            float a = red[t] + red[256 + t] + red[512 + t] + red[768 + t] + b3[t];
            float v = 1.0f / (1.0f + __expf(-a));
            h3s[t] = v;
            g_h3[t] = v;
            // trig rows 0..9 = h3
            #pragma unroll
            for (int r = 0; r < TEMPLATE; r++)
                trig_out[(size_t)r * FDIM + t] = v;
        }
        // zero pa/pb rows 0..9
        if (t < TEMPLATE * HID) {
            g_pa[t] = 0.f;
            g_pb[t] = 0.f;
        }
        return;
    }

    // ================= noise GEMM blocks (16 rows each) =================
    float* tst  = sm;                       // [256][TSTRIDE]
    float* part = sm + FDIM * TSTRIDE;      // [8][16][128]
    int r0 = TEMPLATE + (b - 1) * RPB;

    // prologue: load 0.1*noise (transposed into tst), write trig noise rows
    {
        int k = t & 255, g = t >> 8;        // g in 0..3 -> rows 4g..4g+3
        #pragma unroll
        for (int rr2 = 0; rr2 < 4; rr2++) {
            int rr = 4 * g + rr2;
            int r = r0 + rr;
            if (r < N_NODES) {
                float v = 0.1f * noise[(size_t)(r - TEMPLATE) * FDIM + k];
                tst[k * TSTRIDE + rr] = v;
                trig_out[(size_t)r * FDIM + k] = v;
            } else {
                tst[k * TSTRIDE + rr] = 0.f;
            }
        }
    }
    __syncthreads();

    // GEMM: o = t&127 (half 0 -> pa col, half 1 -> pb col), c = t>>7
    // 8 k-chunks of 32; w preloaded in 2 register batches of 16 (MLP=16).
    {
        int o = t & 127, c = t >> 7;
        int half = o >> 6, oc = o & 63;
        const float* w = ew1 + ((size_t)half * FDIM + c * 32) * HID + oc;
        const float* tb = tst + (c * 32) * TSTRIDE;

        float acc[RPB];
        #pragma unroll
        for (int rr = 0; rr < RPB; rr++) acc[rr] = 0.f;

        #pragma unroll
        for (int batch = 0; batch < 2; batch++) {
            // front-load 16 weight values (16 independent LDGs in flight)
            float wv[16];
            #pragma unroll
            for (int u = 0; u < 16; u++)
                wv[u] = w[(size_t)(batch * 16 + u) * HID];

            #pragma unroll
            for (int u = 0; u < 16; u++) {
                const float* row = tb + (batch * 16 + u) * TSTRIDE;
                float4 rA = *(const float4*)(row);       // rows 0..3 (bcast)
                float4 rB = *(const float4*)(row + 4);   // rows 4..7
                float4 rC = *(const float4*)(row + 8);   // rows 8..11
                float4 rD = *(const float4*)(row + 12);  // rows 12..15
                float wu = wv[u];
                acc[0]  = fmaf(rA.x, wu, acc[0]);
                acc[1]  = fmaf(rA.y, wu, acc[1]);
                acc[2]  = fmaf(rA.z, wu, acc[2]);
                acc[3]  = fmaf(rA.w, wu, acc[3]);
                acc[4]  = fmaf(rB.x, wu, acc[4]);
                acc[5]  = fmaf(rB.y, wu, acc[5]);
                acc[6]  = fmaf(rB.z, wu, acc[6]);
                acc[7]  = fmaf(rB.w, wu, acc[7]);
                acc[8]  = fmaf(rC.x, wu, acc[8]);
                acc[9]  = fmaf(rC.y, wu, acc[9]);
                acc[10] = fmaf(rC.z, wu, acc[10]);
                acc[11] = fmaf(rC.w, wu, acc[11]);
                acc[12] = fmaf(rD.x, wu, acc[12]);
                acc[13] = fmaf(rD.y, wu, acc[13]);
                acc[14] = fmaf(rD.z, wu, acc[14]);
                acc[15] = fmaf(rD.w, wu, acc[15]);
            }
        }
        #pragma unroll
        for (int rr = 0; rr < RPB; rr++)
            part[(c * RPB + rr) * 128 + o] = acc[rr];
    }
    __syncthreads();

    // reduce 8 chunks; 2048 outputs over 1024 threads (2 each)
    {
        #pragma unroll
        for (int u = 0; u < 2; u++) {
            int idx = t + u * 1024;
            int rr = idx >> 7, oo = idx & 127;
            int r = r0 + rr;
            if (r < N_NODES) {
                float s = 0.f;
                #pragma unroll
                for (int c = 0; c < 8; c++)
                    s += part[(c * RPB + rr) * 128 + oo];
                int half = oo >> 6, oc = oo & 63;
                if (half == 0) g_pa[(size_t)r * HID + oc] = s;
                else           g_pb[(size_t)r * HID + oc] = s;
            }
        }
    }
}

// =====================================================================
// gemv_hab: ha = h3 @ ew1[:256] + eb1 ; hb = h3 @ ew1[256:]
// 128 blocks x 256 threads.
// =====================================================================
__global__ __launch_bounds__(256) void gemv_hab(
        const float* __restrict__ ew1, const float* __restrict__ eb1) {
    __shared__ float red[8];
    int b = blockIdx.x;            // 0..127
    int half = b >> 6, oc = b & 63;
    int t = threadIdx.x;           // 0..255

    float v = g_h3[t] * ew1[((size_t)(half * FDIM + t)) * HID + oc];
    #pragma unroll
    for (int off = 16; off > 0; off >>= 1)
        v += __shfl_xor_sync(0xffffffffu, v, off);
    if ((t & 31) == 0) red[t >> 5] = v;
    __syncthreads();
    if (t == 0) {
        float s = red[0] + red[1] + red[2] + red[3] +
                  red[4] + red[5] + red[6] + red[7];
        if (half == 0) g_ha[oc] = s + eb1[oc];
        else           g_hb[oc] = s;
    }
}

// =====================================================================
// Edge kernel: 1D grid. Blocks 0..527 = upper-tri 64x64 tiles;
// blocks 528..543 = trig fixup (trig[10:] += h3, float4).
// =====================================================================
#define TILE 64
#define PADK 68
#define NT   (N_NODES / TILE)         // 32
#define NTILES (NT * (NT + 1) / 2)    // 528
#define NFIX 16

__global__ __launch_bounds__(256) void edge_kernel(const float* __restrict__ ew2,
                                                   const float* __restrict__ eb2,
                                                   float* __restrict__ trig_out,
                                                   float* __restrict__ out) {
    int m = blockIdx.x;
    int tid = threadIdx.x;

    if (m >= NTILES) {
        // -------- trig fixup: trig[10:][:] += h3 (float4) --------
        int f = m - NTILES;                                  // 0..15
        const int total4 = (N_NODES - TEMPLATE) * FDIM / 4;  // 130432
        const int per = (total4 + NFIX - 1) / NFIX;          // 8152
        int s = f * per;
        int e = s + per; if (e > total4) e = total4;
        float4* base = (float4*)(trig_out + (size_t)TEMPLATE * FDIM);
        for (int i = s + tid; i < e; i += 256) {
            int c4 = i & 63;                                 // 64 float4 per row
            float4 h = __ldg((const float4*)&g_h3[c4 * 4]);
            float4 v = base[i];
            v.x += h.x; v.y += h.y; v.z += h.z; v.w += h.w;
            base[i] = v;
        }
        return;
    }

    // decode (bi, bj) with bj >= bi from m
    int bi = (int)(32.5f - sqrtf(32.5f * 32.5f - 2.0f * (float)m));
    while (bi * NT - ((bi * (bi - 1)) >> 1) > m) bi--;
    while ((bi + 1) * NT - (((bi + 1) * bi) >> 1) <= m) bi++;
    int bj = bi + (m - (bi * NT - ((bi * (bi - 1)) >> 1)));

    __shared__ float pa_s[TILE][PADK];
    __shared__ float pb_s[TILE][PADK];
    __shared__ float w2_s[HID];

    const float* paG = g_pa + bi * TILE * HID;
    const float* pbG = g_pb + bj * TILE * HID;
    #pragma unroll
    for (int it = 0; it < 4; it++) {
        int idx = tid + it * 256;
        int row = idx >> 4;
        int kq  = (idx & 15) << 2;
        float4 ha4 = __ldg((const float4*)&g_ha[kq]);
        float4 hb4 = __ldg((const float4*)&g_hb[kq]);
        float4 va = *(const float4*)(paG + row * HID + kq);
        pa_s[row][kq]   = va.x + ha4.x;
        pa_s[row][kq+1] = va.y + ha4.y;
        pa_s[row][kq+2] = va.z + ha4.z;
        pa_s[row][kq+3] = va.w + ha4.w;
        float4 vb = *(const float4*)(pbG + row * HID + kq);
        pb_s[row][kq]   = vb.x + hb4.x;
        pb_s[row][kq+1] = vb.y + hb4.y;
        pb_s[row][kq+2] = vb.z + hb4.z;
        pb_s[row][kq+3] = vb.w + hb4.w;
    }
    if (tid < HID) w2_s[tid] = ew2[tid];
    float c0 = eb2[0];
    __syncthreads();

    int tx = tid & 15;   // j-direction
    int ty = tid >> 4;   // i-direction

    float acc[4][4];
    #pragma unroll
    for (int r = 0; r < 4; r++)
        #pragma unroll
        for (int c = 0; c < 4; c++) acc[r][c] = 0.f;

    #pragma unroll 4
    for (int kq = 0; kq < HID; kq += 4) {
        float4 w4 = *(const float4*)&w2_s[kq];
        float4 A0 = *(const float4*)&pa_s[ty     ][kq];
        float4 A1 = *(const float4*)&pa_s[ty + 16][kq];
        float4 A2 = *(const float4*)&pa_s[ty + 32][kq];
        float4 A3 = *(const float4*)&pa_s[ty + 48][kq];
        float4 B0 = *(const float4*)&pb_s[tx     ][kq];
        float4 B1 = *(const float4*)&pb_s[tx + 16][kq];
        float4 B2 = *(const float4*)&pb_s[tx + 32][kq];
        float4 B3 = *(const float4*)&pb_s[tx + 48][kq];

#define EDGE_STEP(COMP)                                                          \
        {                                                                        \
            float a0 = A0.COMP, a1 = A1.COMP, a2 = A2.COMP, a3 = A3.COMP;        \
            float b0 = B0.COMP, b1 = B1.COMP, b2 = B2.COMP, b3 = B3.COMP;        \
            float w  = w4.COMP;                                                  \
            acc[0][0] = fmaf(fmaxf(a0 + b0, 0.f), w, acc[0][0]);                 \
            acc[0][1] = fmaf(fmaxf(a0 + b1, 0.f), w, acc[0][1]);                 \
            acc[0][2] = fmaf(fmaxf(a0 + b2, 0.f), w, acc[0][2]);                 \
            acc[0][3] = fmaf(fmaxf(a0 + b3, 0.f), w, acc[0][3]);                 \
            acc[1][0] = fmaf(fmaxf(a1 + b0, 0.f), w, acc[1][0]);                 \
            acc[1][1] = fmaf(fmaxf(a1 + b1, 0.f), w, acc[1][1]);                 \
            acc[1][2] = fmaf(fmaxf(a1 + b2, 0.f), w, acc[1][2]);                 \
            acc[1][3] = fmaf(fmaxf(a1 + b3, 0.f), w, acc[1][3]);                 \
            acc[2][0] = fmaf(fmaxf(a2 + b0, 0.f), w, acc[2][0]);                 \
            acc[2][1] = fmaf(fmaxf(a2 + b1, 0.f), w, acc[2][1]);                 \
            acc[2][2] = fmaf(fmaxf(a2 + b2, 0.f), w, acc[2][2]);                 \
            acc[2][3] = fmaf(fmaxf(a2 + b3, 0.f), w, acc[2][3]);                 \
            acc[3][0] = fmaf(fmaxf(a3 + b0, 0.f), w, acc[3][0]);                 \
            acc[3][1] = fmaf(fmaxf(a3 + b1, 0.f), w, acc[3][1]);                 \
            acc[3][2] = fmaf(fmaxf(a3 + b2, 0.f), w, acc[3][2]);                 \
            acc[3][3] = fmaf(fmaxf(a3 + b3, 0.f), w, acc[3][3]);                 \
        }
        EDGE_STEP(x)
        EDGE_STEP(y)
        EDGE_STEP(z)
        EDGE_STEP(w)
#undef EDGE_STEP
    }

    int ibase = bi * TILE;
    int jbase = bj * TILE;
    #pragma unroll
    for (int r = 0; r < 4; r++) {
        int i = ibase + ty + r * 16;
        int off = i * (N_NODES - 1) - ((i * (i - 1)) >> 1) - i - 1;
        #pragma unroll
        for (int c = 0; c < 4; c++) {
            int j = jbase + tx + c * 16;
            if (j > i) {
                out[off + j] = sigmoid_fast(acc[r][c] + c0);
            }
        }
    }
}

// =====================================================================
// Launch
// =====================================================================
extern "C" void kernel_launch(void* const* d_in, const int* in_sizes, int n_in,
                              void* d_out, int out_size) {
    const float* clean_features = (const float*)d_in[0];
    const int*   selected_nodes = (const int*)  d_in[1];
    const float* noise          = (const float*)d_in[2];
    const float* gcn1_w         = (const float*)d_in[3];
    const float* gcn1_b         = (const float*)d_in[4];
    const float* gcn2_w         = (const float*)d_in[5];
    const float* gcn2_b         = (const float*)d_in[6];
    const float* gcn3_w         = (const float*)d_in[7];
    const float* gcn3_b         = (const float*)d_in[8];
    const float* ew1            = (const float*)d_in[9];
    const float* eb1            = (const float*)d_in[10];
    const float* ew2            = (const float*)d_in[11];
    const float* eb2            = (const float*)d_in[12];

    float* out = (float*)d_out;
    float* trig_out = out;                    // [2048, 256]
    float* edge_out = out + N_NODES * FDIM;   // [2096128]

    // idempotent, called every launch (no static guards per harness rules)
    cudaFuncSetAttribute(merged_kernel,
                         cudaFuncAttributeMaxDynamicSharedMemorySize,
                         SMEM_BYTES);

    // 1 gcn block + 128 noise blocks (128*16 = 2048 >= 2038 rows) = one wave
    merged_kernel<<<129, 1024, SMEM_BYTES>>>(
        clean_features, selected_nodes,
        gcn1_w, gcn1_b, gcn2_w, gcn2_b, gcn3_w, gcn3_b,
        noise, ew1, trig_out);

    gemv_hab<<<128, 256>>>(ew1, eb1);

    edge_kernel<<<NTILES + NFIX, 256>>>(ew2, eb2, trig_out, edge_out);
}

// round 12
// speedup vs baseline: 1.5440x; 1.0943x over previous
#include <cuda_runtime.h>
#include <cuda_fp16.h>
#include <cstdint>

#define N_NODES 2048
#define FDIM 256
#define HID 64
#define TEMPLATE 10
#define RPB 16

// -------- scratch (static device globals; no allocation) --------
__device__ float g_h3[FDIM];
__device__ float g_ha[HID];                  // h3 @ ew1[:256] + eb1  (per k)
__device__ float g_hb[HID];                  // h3 @ ew1[256:]        (per k)
__device__ float g_paT[HID * N_NODES];       // [k][node] 0.1*noise@ew1a (cols 0-9 zero)
__device__ float g_pbT[HID * N_NODES];       // [k][node] 0.1*noise@ew1b (cols 0-9 zero)

__device__ __forceinline__ float sigmoid_fast(float x) {
    float t;
    asm("tanh.approx.f32 %0, %1;" : "=f"(t) : "f"(0.5f * x));
    return fmaf(0.5f, t, 0.5f);
}

// =====================================================================
// Merged kernel: block 0 = GCN with smem-staged weights; blocks 1..128 =
// noise GEMM (0.1*noise @ ew1), 16 rows each -> 129 blocks = ONE wave.
// Dynamic smem layout (floats):
//   gcn : w1s 0..16384 | w2s 16384..20480 | w3s 20480..36864 |
//         proto 36864 | red 37120 (4096) | h1 41216 | h2 41280 | h3s 41344
//   noise: tst 0 ([256][20]=5120) | part 5120 ([8][16][129]=16512)
// =====================================================================
#define SMEM_FLOATS 41600
#define SMEM_BYTES  (SMEM_FLOATS * 4)
#define TSTRIDE 20    // 80B row: 16B-aligned for LDS.128
#define PSTRIDE 129   // padded part row: conflict-free strided reduce

extern __shared__ float sm[];

__global__ __launch_bounds__(1024) void merged_kernel(
        const float* __restrict__ cf,  const int* __restrict__ sel,
        const float* __restrict__ w1, const float* __restrict__ b1,
        const float* __restrict__ w2, const float* __restrict__ b2,
        const float* __restrict__ w3, const float* __restrict__ b3,
        const float* __restrict__ noise,
        const float* __restrict__ ew1,
        float* __restrict__ trig_out) {
    int t = threadIdx.x;  // 0..1023
    int b = blockIdx.x;

    if (b == 0) {
        // ================= GCN block =================
        float* w1s   = sm;
        float* w2s   = sm + 16384;
        float* w3s   = sm + 20480;
        float* proto = sm + 36864;
        float* red   = sm + 37120;
        float* h1    = sm + 41216;
        float* h2    = sm + 41280;
        float* h3s   = sm + 41344;

        int sidx[TEMPLATE];
        #pragma unroll
        for (int q = 0; q < TEMPLATE; q++) sidx[q] = sel[q];

        // stream all weights to smem (coalesced float4)
        #pragma unroll
        for (int i = 0; i < 4; i++) {
            int idx = t + i * 1024;
            ((float4*)w1s)[idx] = ((const float4*)w1)[idx];
        }
        ((float4*)w2s)[t] = ((const float4*)w2)[t];
        #pragma unroll
        for (int i = 0; i < 4; i++) {
            int idx = t + i * 1024;
            ((float4*)w3s)[idx] = ((const float4*)w3)[idx];
        }

        if (t < FDIM) {
            float s = 0.f;
            #pragma unroll
            for (int q = 0; q < TEMPLATE; q++)
                s += cf[(size_t)sidx[q] * FDIM + t];
            proto[t] = s * (1.0f / TEMPLATE);
        }
        __syncthreads();

        int o1 = t & 63, kq1 = t >> 6;   // 16 chunks

        // layer1: 256 -> 64
        {
            float a0 = 0.f, a1 = 0.f, a2 = 0.f, a3 = 0.f;
            int kb = kq1 * 16;
            #pragma unroll
            for (int kk = 0; kk < 16; kk += 4) {
                a0 = fmaf(proto[kb+kk],   w1s[(kb+kk)  *HID + o1], a0);
                a1 = fmaf(proto[kb+kk+1], w1s[(kb+kk+1)*HID + o1], a1);
                a2 = fmaf(proto[kb+kk+2], w1s[(kb+kk+2)*HID + o1], a2);
                a3 = fmaf(proto[kb+kk+3], w1s[(kb+kk+3)*HID + o1], a3);
            }
            red[kq1 * 64 + o1] = (a0 + a1) + (a2 + a3);
        }
        __syncthreads();
        if (t < HID) {
            float s = b1[t];
            #pragma unroll
            for (int c = 0; c < 16; c++) s += red[c * 64 + t];
            h1[t] = fmaxf(s, 0.f);
        }
        __syncthreads();

        // layer2: 64 -> 64
        {
            int kb = kq1 * 4;
            float a0 = fmaf(h1[kb],   w2s[(kb)  *HID + o1], 0.f);
            float a1 = fmaf(h1[kb+1], w2s[(kb+1)*HID + o1], 0.f);
            a0 = fmaf(h1[kb+2], w2s[(kb+2)*HID + o1], a0);
            a1 = fmaf(h1[kb+3], w2s[(kb+3)*HID + o1], a1);
            red[kq1 * 64 + o1] = a0 + a1;
        }
        __syncthreads();
        if (t < HID) {
            float s = b2[t];
            #pragma unroll
            for (int c = 0; c < 16; c++) s += red[c * 64 + t];
            h2[t] = fmaxf(s, 0.f);
        }
        __syncthreads();

        // layer3: 64 -> 256
        {
            int o3 = t & 255, kh3 = t >> 8;
            int kb = kh3 * 16;
            float a0 = 0.f, a1 = 0.f, a2 = 0.f, a3 = 0.f;
            #pragma unroll
            for (int kk = 0; kk < 16; kk += 4) {
                a0 = fmaf(h2[kb+kk],   w3s[(kb+kk)  *FDIM + o3], a0);
                a1 = fmaf(h2[kb+kk+1], w3s[(kb+kk+1)*FDIM + o3], a1);
                a2 = fmaf(h2[kb+kk+2], w3s[(kb+kk+2)*FDIM + o3], a2);
                a3 = fmaf(h2[kb+kk+3], w3s[(kb+kk+3)*FDIM + o3], a3);
            }
            red[kh3 * 256 + o3] = (a0 + a1) + (a2 + a3);
        }
        __syncthreads();
        if (t < FDIM) {
            float a = red[t] + red[256 + t] + red[512 + t] + red[768 + t] + b3[t];
            float v = 1.0f / (1.0f + __expf(-a));
            h3s[t] = v;
            g_h3[t] = v;
            #pragma unroll
            for (int r = 0; r < TEMPLATE; r++)
                trig_out[(size_t)r * FDIM + t] = v;
        }
        // zero paT/pbT columns 0..9 (all 64 k rows)
        if (t < HID * TEMPLATE) {
            int k = t / TEMPLATE, node = t % TEMPLATE;
            g_paT[(size_t)k * N_NODES + node] = 0.f;
            g_pbT[(size_t)k * N_NODES + node] = 0.f;
        }
        return;
    }

    // ================= noise GEMM blocks (16 rows each) =================
    float* tst  = sm;                       // [256][TSTRIDE]
    float* part = sm + FDIM * TSTRIDE;      // [8][16][PSTRIDE]
    int r0 = TEMPLATE + (b - 1) * RPB;

    // prologue: load 0.1*noise (transposed into tst), write trig noise rows
    {
        int k = t & 255, g = t >> 8;        // g in 0..3 -> rows 4g..4g+3
        #pragma unroll
        for (int rr2 = 0; rr2 < 4; rr2++) {
            int rr = 4 * g + rr2;
            int r = r0 + rr;
            if (r < N_NODES) {
                float v = 0.1f * noise[(size_t)(r - TEMPLATE) * FDIM + k];
                tst[k * TSTRIDE + rr] = v;
                trig_out[(size_t)r * FDIM + k] = v;
            } else {
                tst[k * TSTRIDE + rr] = 0.f;
            }
        }
    }
    __syncthreads();

    // GEMM: o = t&127 (half 0 -> pa col, half 1 -> pb col), c = t>>7
    {
        int o = t & 127, c = t >> 7;
        int half = o >> 6, oc = o & 63;
        const float* w = ew1 + ((size_t)half * FDIM + c * 32) * HID + oc;
        const float* tb = tst + (c * 32) * TSTRIDE;

        float acc[RPB];
        #pragma unroll
        for (int rr = 0; rr < RPB; rr++) acc[rr] = 0.f;

        #pragma unroll 4
        for (int kk = 0; kk < 32; kk++) {
            float wv = w[(size_t)kk * HID];
            const float* row = tb + kk * TSTRIDE;
            float4 rA = *(const float4*)(row);
            float4 rB = *(const float4*)(row + 4);
            float4 rC = *(const float4*)(row + 8);
            float4 rD = *(const float4*)(row + 12);
            acc[0]  = fmaf(rA.x, wv, acc[0]);
            acc[1]  = fmaf(rA.y, wv, acc[1]);
            acc[2]  = fmaf(rA.z, wv, acc[2]);
            acc[3]  = fmaf(rA.w, wv, acc[3]);
            acc[4]  = fmaf(rB.x, wv, acc[4]);
            acc[5]  = fmaf(rB.y, wv, acc[5]);
            acc[6]  = fmaf(rB.z, wv, acc[6]);
            acc[7]  = fmaf(rB.w, wv, acc[7]);
            acc[8]  = fmaf(rC.x, wv, acc[8]);
            acc[9]  = fmaf(rC.y, wv, acc[9]);
            acc[10] = fmaf(rC.z, wv, acc[10]);
            acc[11] = fmaf(rC.w, wv, acc[11]);
            acc[12] = fmaf(rD.x, wv, acc[12]);
            acc[13] = fmaf(rD.y, wv, acc[13]);
            acc[14] = fmaf(rD.z, wv, acc[14]);
            acc[15] = fmaf(rD.w, wv, acc[15]);
        }
        #pragma unroll
        for (int rr = 0; rr < RPB; rr++)
            part[(c * RPB + rr) * PSTRIDE + o] = acc[rr];
    }
    __syncthreads();

    // reduce 8 chunks; TRANSPOSED store to g_paT/g_pbT[k][node]
    {
        #pragma unroll
        for (int u = 0; u < 2; u++) {
            int idx = t + u * 1024;
            int rr = idx & 15, oo = idx >> 4;   // lanes vary rr -> node-contig
            int r = r0 + rr;
            if (r < N_NODES) {
                float s = 0.f;
                #pragma unroll
                for (int c = 0; c < 8; c++)
                    s += part[(c * RPB + rr) * PSTRIDE + oo];
                int half = oo >> 6, oc = oo & 63;
                if (half == 0) g_paT[(size_t)oc * N_NODES + r] = s;
                else           g_pbT[(size_t)oc * N_NODES + r] = s;
            }
        }
    }
}

// =====================================================================
// gemv_hab: ha = h3 @ ew1[:256] + eb1 ; hb = h3 @ ew1[256:]
// =====================================================================
__global__ __launch_bounds__(256) void gemv_hab(
        const float* __restrict__ ew1, const float* __restrict__ eb1) {
    __shared__ float red[8];
    int b = blockIdx.x;            // 0..127
    int half = b >> 6, oc = b & 63;
    int t = threadIdx.x;           // 0..255

    float v = g_h3[t] * ew1[((size_t)(half * FDIM + t)) * HID + oc];
    #pragma unroll
    for (int off = 16; off > 0; off >>= 1)
        v += __shfl_xor_sync(0xffffffffu, v, off);
    if ((t & 31) == 0) red[t >> 5] = v;
    __syncthreads();
    if (t == 0) {
        float s = red[0] + red[1] + red[2] + red[3] +
                  red[4] + red[5] + red[6] + red[7];
        if (half == 0) g_ha[oc] = s + eb1[oc];
        else           g_hb[oc] = s;
    }
}

// =====================================================================
// Edge kernel (fp16x2 math): blocks 0..527 = upper-tri 64x64 tiles;
// blocks 528..543 = trig fixup. 256 threads, per-thread 4i x 4j.
// smem tiles in half, k-major; acc = 4 interleaved fp16 partials,
// combined in fp32 before sigmoid.
// =====================================================================
#define TILE 64
#define HPAD 72                       // half-row stride
#define NT   (N_NODES / TILE)         // 32
#define NTILES (NT * (NT + 1) / 2)    // 528
#define NFIX 16

__global__ __launch_bounds__(256) void edge_kernel(const float* __restrict__ ew2,
                                                   const float* __restrict__ eb2,
                                                   float* __restrict__ trig_out,
                                                   float* __restrict__ out) {
    int m = blockIdx.x;
    int tid = threadIdx.x;

    if (m >= NTILES) {
        // -------- trig fixup: trig[10:][:] += h3 (float4) --------
        int f = m - NTILES;                                  // 0..15
        const int total4 = (N_NODES - TEMPLATE) * FDIM / 4;  // 130432
        const int per = (total4 + NFIX - 1) / NFIX;
        int s = f * per;
        int e = s + per; if (e > total4) e = total4;
        float4* base = (float4*)(trig_out + (size_t)TEMPLATE * FDIM);
        for (int i = s + tid; i < e; i += 256) {
            int c4 = i & 63;
            float4 h = __ldg((const float4*)&g_h3[c4 * 4]);
            float4 v = base[i];
            v.x += h.x; v.y += h.y; v.z += h.z; v.w += h.w;
            base[i] = v;
        }
        return;
    }

    // decode (bi, bj) with bj >= bi from m
    int bi = (int)(32.5f - sqrtf(32.5f * 32.5f - 2.0f * (float)m));
    while (bi * NT - ((bi * (bi - 1)) >> 1) > m) bi--;
    while ((bi + 1) * NT - (((bi + 1) * bi) >> 1) <= m) bi++;
    int bj = bi + (m - (bi * NT - ((bi * (bi - 1)) >> 1)));

    __shared__ __half pah[HID][HPAD];     // [k][i], +ha folded, 9.2KB
    __shared__ __half pbh[HID][HPAD];     // [k][j], +hb folded
    __shared__ __half2 w2h[HID];          // (w,w) pairs

    // tile load: g_paT/g_pbT are [k][node] float; convert to half
    {
        const float* paG = g_paT + (size_t)bi * TILE;
        const float* pbG = g_pbT + (size_t)bj * TILE;
        #pragma unroll
        for (int it = 0; it < 4; it++) {
            int idx = tid + it * 256;     // 1024 slots: k = idx>>4, c4
            int k = idx >> 4;
            int c4 = (idx & 15) << 2;
            float hav = __ldg(&g_ha[k]);
            float hbv = __ldg(&g_hb[k]);
            float4 va = *(const float4*)(paG + (size_t)k * N_NODES + c4);
            __half2 pa01 = __floats2half2_rn(va.x + hav, va.y + hav);
            __half2 pa23 = __floats2half2_rn(va.z + hav, va.w + hav);
            *(__half2*)&pah[k][c4]     = pa01;
            *(__half2*)&pah[k][c4 + 2] = pa23;
            float4 vb = *(const float4*)(pbG + (size_t)k * N_NODES + c4);
            __half2 pb01 = __floats2half2_rn(vb.x + hbv, vb.y + hbv);
            __half2 pb23 = __floats2half2_rn(vb.z + hbv, vb.w + hbv);
            *(__half2*)&pbh[k][c4]     = pb01;
            *(__half2*)&pbh[k][c4 + 2] = pb23;
        }
        if (tid < HID) w2h[tid] = __float2half2_rn(ew2[tid]);
    }
    float c0 = eb2[0];
    __syncthreads();

    int tx = tid & 15;   // j-group: j = 4*tx + (0..3)
    int ty = tid >> 4;   // i-group: i = 4*ty + (0..3)

    const __half2 zero2 = __float2half2_rn(0.0f);
    // acc[group][i][jp]: 4 interleaved 16-term fp16 partial sums
    __half2 acc[4][4][2];
    #pragma unroll
    for (int g = 0; g < 4; g++)
        #pragma unroll
        for (int i = 0; i < 4; i++) {
            acc[g][i][0] = zero2;
            acc[g][i][1] = zero2;
        }

    #pragma unroll 4
    for (int k = 0; k < HID; k++) {
        int g = k & 3;
        __half2 wk = w2h[k];
        __half2 a01 = *(const __half2*)&pah[k][4 * ty];
        __half2 a23 = *(const __half2*)&pah[k][4 * ty + 2];
        __half2 b01 = *(const __half2*)&pbh[k][4 * tx];
        __half2 b23 = *(const __half2*)&pbh[k][4 * tx + 2];
        __half2 ai[4];
        ai[0] = __lows2half2(a01, a01);
        ai[1] = __highs2half2(a01, a01);
        ai[2] = __lows2half2(a23, a23);
        ai[3] = __highs2half2(a23, a23);
        #pragma unroll
        for (int i = 0; i < 4; i++) {
            __half2 s0 = __hmax2(__hadd2(ai[i], b01), zero2);
            __half2 s1 = __hmax2(__hadd2(ai[i], b23), zero2);
            acc[g][i][0] = __hfma2(s0, wk, acc[g][i][0]);
            acc[g][i][1] = __hfma2(s1, wk, acc[g][i][1]);
        }
    }

    int ibase = bi * TILE;
    int jbase = bj * TILE;
    #pragma unroll
    for (int i = 0; i < 4; i++) {
        int ii = ibase + 4 * ty + i;
        // linear index of (ii,j) in row-major upper triangle (k=1)
        int off = ii * (N_NODES - 1) - ((ii * (ii - 1)) >> 1) - ii - 1;
        #pragma unroll
        for (int jp = 0; jp < 2; jp++) {
            float2 s = make_float2(0.f, 0.f);
            #pragma unroll
            for (int g = 0; g < 4; g++) {
                float2 p = __half22float2(acc[g][i][jp]);
                s.x += p.x; s.y += p.y;
            }
            int j0 = jbase + 4 * tx + 2 * jp;
            if (j0     > ii) out[off + j0]     = sigmoid_fast(s.x + c0);
            if (j0 + 1 > ii) out[off + j0 + 1] = sigmoid_fast(s.y + c0);
        }
    }
}

// =====================================================================
// Launch
// =====================================================================
extern "C" void kernel_launch(void* const* d_in, const int* in_sizes, int n_in,
                              void* d_out, int out_size) {
    const float* clean_features = (const float*)d_in[0];
    const int*   selected_nodes = (const int*)  d_in[1];
    const float* noise          = (const float*)d_in[2];
    const float* gcn1_w         = (const float*)d_in[3];
    const float* gcn1_b         = (const float*)d_in[4];
    const float* gcn2_w         = (const float*)d_in[5];
    const float* gcn2_b         = (const float*)d_in[6];
    const float* gcn3_w         = (const float*)d_in[7];
    const float* gcn3_b         = (const float*)d_in[8];
    const float* ew1            = (const float*)d_in[9];
    const float* eb1            = (const float*)d_in[10];
    const float* ew2            = (const float*)d_in[11];
    const float* eb2            = (const float*)d_in[12];

    float* out = (float*)d_out;
    float* trig_out = out;                    // [2048, 256]
    float* edge_out = out + N_NODES * FDIM;   // [2096128]

    cudaFuncSetAttribute(merged_kernel,
                         cudaFuncAttributeMaxDynamicSharedMemorySize,
                         SMEM_BYTES);

    merged_kernel<<<129, 1024, SMEM_BYTES>>>(
        clean_features, selected_nodes,
        gcn1_w, gcn1_b, gcn2_w, gcn2_b, gcn3_w, gcn3_b,
        noise, ew1, trig_out);

    gemv_hab<<<128, 256>>>(ew1, eb1);

    edge_kernel<<<NTILES + NFIX, 256>>>(ew2, eb2, trig_out, edge_out);
}